// round 6
// baseline (speedup 1.0000x reference)
#include <cuda_runtime.h>
#include <math.h>

#define THREADS 256
typedef unsigned long long ull;

// ---- shared memory layout (float offsets) ----
// ws: double-buffered 8-k weight chunks, k-major rows of 256 floats padded to 260
#define XBUF_OFF 0            // [64][256] activations
#define EMB_OFF  16384        // [64][64]  xyz harmonic emb (cols 0..31 reused for dir emb)
#define WS_OFF   20480        // float[2][8][260]
#define WS_BUF   2080         // floats per buffer
#define DENS_OFF 24640        // [64]
#define EMBD_OFF 24704        // [32]
#define SMEM_FLOATS 24736
#define SMEM_BYTES (SMEM_FLOATS * 4)   // 98,944 B -> 2 CTAs/SM fit in 228KB carveout

__device__ __forceinline__ void fma2(ull& d, ull a, ull b) {
    asm("fma.rn.f32x2 %0, %1, %2, %0;" : "+l"(d) : "l"(a), "l"(b));
}
__device__ __forceinline__ ull pack2(float lo, float hi) {
    ull r; asm("mov.b64 %0, {%1, %2};" : "=l"(r) : "f"(lo), "f"(hi)); return r;
}
__device__ __forceinline__ void unpack2(ull v, float& lo, float& hi) {
    asm("mov.b64 {%0, %1}, %2;" : "=f"(lo), "=f"(hi) : "l"(v));
}

// Stage one 8-wide k-chunk of W (OUTW rows) into dst (k-major, stride 260, o-fast).
// Lanes k-fast (4 float2 per o-row) -> 32B contiguous LDG segments, full sectors.
// STS banks: (2*kk2)*260 + o -> k in {0,2,4,6} maps to disjoint 8-bank groups: conflict-free.
template<int OUTW>
__device__ __forceinline__ void stage_chunk(const float* __restrict__ Wg, int in_act,
                                            int k0, float* __restrict__ dst, int tid) {
    const bool aligned = ((in_act & 1) == 0);
#pragma unroll 1
    for (int idx = tid; idx < OUTW * 4; idx += THREADS) {
        int kk2 = idx & 3;
        int o   = idx >> 2;
        int k   = k0 + (kk2 << 1);
        const float* row = Wg + o * in_act;
        float2 v;
        if (aligned && (k + 1 < in_act)) {
            v = __ldg(reinterpret_cast<const float2*>(row + k));
        } else {
            v.x = (k     < in_act) ? __ldg(row + k)     : 0.0f;
            v.y = (k + 1 < in_act) ? __ldg(row + k + 1) : 0.0f;
        }
        dst[(kk2 << 1) * 260 + o]       = v.x;
        dst[((kk2 << 1) + 1) * 260 + o] = v.y;
    }
}

// Fused layer: xbuf[64][OUT] = relu(A * W^T + b), OUT = NJ*64.
// 8 warps, per-thread tile 8m x (NJ o-pairs): acc ull = outputs (2op, 2op+1),
// op = lane + 32j. Activation scalar duplicated into both halves. acc = 64 regs (NJ=4).
template<int NJ>
__device__ __forceinline__ void gemm_layer(
    const float* __restrict__ Wg, const float* __restrict__ bg,
    int in_act, int nchunks, int xchunks,
    float* xbuf, float* emb, float* ws)
{
    const int tid  = threadIdx.x;
    const int lane = tid & 31;
    const int mb   = (tid >> 5) << 3;

    ull acc[8][NJ];
#pragma unroll
    for (int j = 0; j < NJ; ++j) {
        float2 b2 = __ldg(reinterpret_cast<const float2*>(bg) + lane + (j << 5));
        ull bv = pack2(b2.x, b2.y);
#pragma unroll
        for (int i = 0; i < 8; ++i) acc[i][j] = bv;
    }

    stage_chunk<NJ * 64>(Wg, in_act, 0, ws, tid);   // prologue into buffer 0

#pragma unroll 1
    for (int c = 0; c < nchunks; ++c) {
        __syncthreads();   // chunk c staged; prior reads of other buffer finished
        if (c + 1 < nchunks)
            stage_chunk<NJ * 64>(Wg, in_act, (c + 1) << 3, ws + ((c + 1) & 1) * WS_BUF, tid);

        const float* As; int lda;
        if (c < xchunks) { As = xbuf + (c << 3);             lda = 256; }
        else             { As = emb  + ((c - xchunks) << 3); lda = 64;  }
        const float* wb = ws + (c & 1) * WS_BUF;

#pragma unroll
        for (int kp = 0; kp < 4; ++kp) {            // 4 k-pairs per 8-k chunk
            ull we[NJ], wo[NJ];
#pragma unroll
            for (int j = 0; j < NJ; ++j) {          // lane-consecutive 8B: conflict-free
                we[j] = *reinterpret_cast<const ull*>(wb + (kp << 1) * 260 + ((lane + (j << 5)) << 1));
                wo[j] = *reinterpret_cast<const ull*>(wb + ((kp << 1) + 1) * 260 + ((lane + (j << 5)) << 1));
            }
#pragma unroll
            for (int i = 0; i < 8; ++i) {
                float2 av = *reinterpret_cast<const float2*>(As + (mb + i) * lda + (kp << 1));
                ull ae = pack2(av.x, av.x);
                ull ao = pack2(av.y, av.y);
#pragma unroll
                for (int j = 0; j < NJ; ++j) fma2(acc[i][j], ae, we[j]);
#pragma unroll
                for (int j = 0; j < NJ; ++j) fma2(acc[i][j], ao, wo[j]);
            }
        }
    }
    __syncthreads();   // all reads of xbuf/ws done before overwrite
#pragma unroll
    for (int j = 0; j < NJ; ++j) {
        const int o2 = (lane + (j << 5)) << 1;
#pragma unroll
        for (int i = 0; i < 8; ++i) {
            float lo, hi;
            unpack2(acc[i][j], lo, hi);
            float2 r;
            r.x = fmaxf(lo, 0.0f);
            r.y = fmaxf(hi, 0.0f);
            *reinterpret_cast<float2*>(xbuf + (mb + i) * 256 + o2) = r;   // 8B lane-consecutive
        }
    }
    __syncthreads();
}

__global__ void __launch_bounds__(THREADS, 2) nerf_fused(
    const float* __restrict__ sp,   const float* __restrict__ dirs,
    const float* __restrict__ Wx0,  const float* __restrict__ bx0,
    const float* __restrict__ Wx1,  const float* __restrict__ bx1,
    const float* __restrict__ Wx2,  const float* __restrict__ bx2,
    const float* __restrict__ Wx3,  const float* __restrict__ bx3,
    const float* __restrict__ Wx4,  const float* __restrict__ bx4,
    const float* __restrict__ Wx5,  const float* __restrict__ bx5,
    const float* __restrict__ Wx6,  const float* __restrict__ bx6,
    const float* __restrict__ Wx7,  const float* __restrict__ bx7,
    const float* __restrict__ Wd0,  const float* __restrict__ bd0,
    const float* __restrict__ Wden, const float* __restrict__ bden,
    const float* __restrict__ Wfeat,const float* __restrict__ bfeat,
    const float* __restrict__ Wrgb, const float* __restrict__ brgb,
    float* __restrict__ out)
{
    extern __shared__ float sm[];
    float* xbuf = sm + XBUF_OFF;
    float* emb  = sm + EMB_OFF;
    float* ws   = sm + WS_OFF;
    float* dens = sm + DENS_OFF;
    float* embd = sm + EMBD_OFF;

    const int tid  = threadIdx.x;
    const int lane = tid & 31;
    const int warp = tid >> 5;
    const int p0   = blockIdx.x << 6;   // one ray (64 samples) per block

    // ---- Phase 0: xyz harmonic embedding [sin(30), cos(30), xyz(3), pad0] ----
    if (tid < 64) {
        const float* pp = sp + (size_t)(p0 + tid) * 3;
        float* e = emb + tid * 64;
#pragma unroll
        for (int d = 0; d < 3; ++d) {
            float x = pp[d];
            float f = 1.0f;
#pragma unroll
            for (int h = 0; h < 10; ++h) {
                float s, c;
                sincosf(x * f, &s, &c);
                e[d * 10 + h]      = s;
                e[30 + d * 10 + h] = c;
                f *= 2.0f;
            }
            e[60 + d] = x;
        }
        e[63] = 0.0f;
    }
    // gemm_layer's loop-top __syncthreads orders phase 0 vs first compute

    gemm_layer<4>(Wx0, bx0,  63,  8, 0,  xbuf, emb, ws);   // 63->256 (from emb)
    gemm_layer<4>(Wx1, bx1, 256, 32, 32, xbuf, emb, ws);
    gemm_layer<4>(Wx2, bx2, 256, 32, 32, xbuf, emb, ws);
    gemm_layer<4>(Wx3, bx3, 256, 32, 32, xbuf, emb, ws);
    gemm_layer<4>(Wx4, bx4, 319, 40, 32, xbuf, emb, ws);   // skip: [h(256), emb_x(63)]
    gemm_layer<4>(Wx5, bx5, 256, 32, 32, xbuf, emb, ws);
    gemm_layer<4>(Wx6, bx6, 256, 32, 32, xbuf, emb, ws);
    gemm_layer<4>(Wx7, bx7, 256, 32, 32, xbuf, emb, ws);

    // ---- density head (reads xbuf before feat overwrites it) ----
    {
        const float bd = __ldg(bden);
#pragma unroll 1
        for (int it = 0; it < 8; ++it) {
            int m = warp + (it << 3);
            float s = 0.0f;
#pragma unroll
            for (int kk = 0; kk < 8; ++kk) {
                int k = lane + (kk << 5);
                s += xbuf[m * 256 + k] * __ldg(Wden + k);
            }
#pragma unroll
            for (int off = 16; off > 0; off >>= 1) s += __shfl_xor_sync(0xffffffffu, s, off);
            if (lane == 0) dens[m] = fmaxf(s + bd, 0.0f);
        }
    }
    __syncthreads();

    gemm_layer<4>(Wfeat, bfeat, 256, 32, 32, xbuf, emb, ws);

    // ---- direction embedding [sin(12), cos(12), dir(3), pad0] -> emb cols 0..31 ----
    if (tid < 32) {
        float v = 0.0f;
        if (tid < 12) {
            float x = __ldg(dirs + blockIdx.x * 3 + (tid >> 2));
            v = sinf(x * (float)(1 << (tid & 3)));
        } else if (tid < 24) {
            int kk = tid - 12;
            float x = __ldg(dirs + blockIdx.x * 3 + (kk >> 2));
            v = cosf(x * (float)(1 << (kk & 3)));
        } else if (tid < 27) {
            v = __ldg(dirs + blockIdx.x * 3 + (tid - 24));
        }
        embd[tid] = v;
    }
    __syncthreads();
    for (int idx = tid; idx < 64 * 32; idx += THREADS)
        emb[(idx >> 5) * 64 + (idx & 31)] = embd[idx & 31];

    gemm_layer<2>(Wd0, bd0, 283, 36, 32, xbuf, emb, ws);   // [feat(256), emb_d(27)] -> 128

    // ---- rgb head + output ----
    {
#pragma unroll 1
        for (int it = 0; it < 8; ++it) {
            int m = warp + (it << 3);
            float s0 = 0.0f, s1 = 0.0f, s2 = 0.0f;
#pragma unroll
            for (int kk = 0; kk < 4; ++kk) {
                int k = lane + (kk << 5);
                float h = xbuf[m * 256 + k];
                s0 += h * __ldg(Wrgb + k);
                s1 += h * __ldg(Wrgb + 128 + k);
                s2 += h * __ldg(Wrgb + 256 + k);
            }
#pragma unroll
            for (int off = 16; off > 0; off >>= 1) {
                s0 += __shfl_xor_sync(0xffffffffu, s0, off);
                s1 += __shfl_xor_sync(0xffffffffu, s1, off);
                s2 += __shfl_xor_sync(0xffffffffu, s2, off);
            }
            if (lane == 0) {
                float* op = out + (size_t)(p0 + m) * 4;
                op[0] = dens[m];
                op[1] = 1.0f / (1.0f + expf(-(s0 + __ldg(brgb))));
                op[2] = 1.0f / (1.0f + expf(-(s1 + __ldg(brgb + 1))));
                op[3] = 1.0f / (1.0f + expf(-(s2 + __ldg(brgb + 2))));
            }
        }
    }
}

extern "C" void kernel_launch(void* const* d_in, const int* in_sizes, int n_in,
                              void* d_out, int out_size) {
    (void)in_sizes; (void)n_in; (void)out_size;
    cudaFuncSetAttribute(nerf_fused, cudaFuncAttributeMaxDynamicSharedMemorySize, SMEM_BYTES);
    nerf_fused<<<4096, THREADS, SMEM_BYTES>>>(
        (const float*)d_in[0],  (const float*)d_in[1],
        (const float*)d_in[2],  (const float*)d_in[3],
        (const float*)d_in[4],  (const float*)d_in[5],
        (const float*)d_in[6],  (const float*)d_in[7],
        (const float*)d_in[8],  (const float*)d_in[9],
        (const float*)d_in[10], (const float*)d_in[11],
        (const float*)d_in[12], (const float*)d_in[13],
        (const float*)d_in[14], (const float*)d_in[15],
        (const float*)d_in[16], (const float*)d_in[17],
        (const float*)d_in[18], (const float*)d_in[19],
        (const float*)d_in[20], (const float*)d_in[21],
        (const float*)d_in[22], (const float*)d_in[23],
        (const float*)d_in[24], (const float*)d_in[25],
        (float*)d_out);
}

// round 7
// speedup vs baseline: 1.6264x; 1.6264x over previous
#include <cuda_runtime.h>
#include <math.h>

#define THREADS 256
typedef unsigned long long ull;

// ---- shared memory layout (float offsets) ----
// ws: double-buffered 8-k weight chunks, k-major rows of 256 floats padded to 260
#define XBUF_OFF 0            // [64][256] activations
#define EMB_OFF  16384        // [64][64]  xyz harmonic emb (cols 0..31 reused for dir emb)
#define WS_OFF   20480        // float[2][8][260]
#define WS_BUF   2080         // floats per buffer
#define DENS_OFF 24640        // [64]
#define EMBD_OFF 24704        // [32]
#define SMEM_FLOATS 24736
#define SMEM_BYTES (SMEM_FLOATS * 4)   // 98,944 B -> 2 CTAs/SM fit in 228KB carveout

__device__ __forceinline__ void fma2(ull& d, ull a, ull b) {
    asm("fma.rn.f32x2 %0, %1, %2, %0;" : "+l"(d) : "l"(a), "l"(b));
}
__device__ __forceinline__ ull pack2(float lo, float hi) {
    ull r; asm("mov.b64 %0, {%1, %2};" : "=l"(r) : "f"(lo), "f"(hi)); return r;
}
__device__ __forceinline__ void unpack2(ull v, float& lo, float& hi) {
    asm("mov.b64 {%0, %1}, %2;" : "=f"(lo), "=f"(hi) : "l"(v));
}

// Stage one 8-wide k-chunk of W (OUTW rows) into dst (k-major, stride 260, o-fast).
// Lanes k-fast (4 float2 per o-row) -> 32B contiguous LDG segments, full sectors.
// STS banks: (2*kk2)*260 + o -> k in {0,2,4,6} maps to disjoint 8-bank groups: conflict-free.
template<int OUTW>
__device__ __forceinline__ void stage_chunk(const float* __restrict__ Wg, int in_act,
                                            int k0, float* __restrict__ dst, int tid) {
    const bool aligned = ((in_act & 1) == 0);
#pragma unroll 1
    for (int idx = tid; idx < OUTW * 4; idx += THREADS) {
        int kk2 = idx & 3;
        int o   = idx >> 2;
        int k   = k0 + (kk2 << 1);
        const float* row = Wg + o * in_act;
        float2 v;
        if (aligned && (k + 1 < in_act)) {
            v = __ldg(reinterpret_cast<const float2*>(row + k));
        } else {
            v.x = (k     < in_act) ? __ldg(row + k)     : 0.0f;
            v.y = (k + 1 < in_act) ? __ldg(row + k + 1) : 0.0f;
        }
        dst[(kk2 << 1) * 260 + o]       = v.x;
        dst[((kk2 << 1) + 1) * 260 + o] = v.y;
    }
}

// Fused layer: xbuf[64][OUT] = relu(A * W^T + b), OUT = NJ*64.
// 8 warps, per-thread tile 8m x (NJ o-pairs): acc ull = outputs (2op, 2op+1),
// op = lane + 32j. Activation scalar duplicated into both halves. acc = 64 regs (NJ=4).
template<int NJ>
__device__ __forceinline__ void gemm_layer(
    const float* __restrict__ Wg, const float* __restrict__ bg,
    int in_act, int nchunks, int xchunks,
    float* xbuf, float* emb, float* ws)
{
    const int tid  = threadIdx.x;
    const int lane = tid & 31;
    const int mb   = (tid >> 5) << 3;

    ull acc[8][NJ];
#pragma unroll
    for (int j = 0; j < NJ; ++j) {
        float2 b2 = __ldg(reinterpret_cast<const float2*>(bg) + lane + (j << 5));
        ull bv = pack2(b2.x, b2.y);
#pragma unroll
        for (int i = 0; i < 8; ++i) acc[i][j] = bv;
    }

    stage_chunk<NJ * 64>(Wg, in_act, 0, ws, tid);   // prologue into buffer 0

#pragma unroll 1
    for (int c = 0; c < nchunks; ++c) {
        __syncthreads();   // chunk c staged; prior reads of other buffer finished
        if (c + 1 < nchunks)
            stage_chunk<NJ * 64>(Wg, in_act, (c + 1) << 3, ws + ((c + 1) & 1) * WS_BUF, tid);

        const float* As; int lda;
        if (c < xchunks) { As = xbuf + (c << 3);             lda = 256; }
        else             { As = emb  + ((c - xchunks) << 3); lda = 64;  }
        const float* wb = ws + (c & 1) * WS_BUF;

#pragma unroll
        for (int kp = 0; kp < 4; ++kp) {            // 4 k-pairs per 8-k chunk
            ull we[NJ], wo[NJ];
#pragma unroll
            for (int j = 0; j < NJ; ++j) {          // lane-consecutive 8B: conflict-free
                we[j] = *reinterpret_cast<const ull*>(wb + (kp << 1) * 260 + ((lane + (j << 5)) << 1));
                wo[j] = *reinterpret_cast<const ull*>(wb + ((kp << 1) + 1) * 260 + ((lane + (j << 5)) << 1));
            }
#pragma unroll
            for (int i = 0; i < 8; ++i) {
                float2 av = *reinterpret_cast<const float2*>(As + (mb + i) * lda + (kp << 1));
                ull ae = pack2(av.x, av.x);
                ull ao = pack2(av.y, av.y);
#pragma unroll
                for (int j = 0; j < NJ; ++j) fma2(acc[i][j], ae, we[j]);
#pragma unroll
                for (int j = 0; j < NJ; ++j) fma2(acc[i][j], ao, wo[j]);
            }
        }
    }
    __syncthreads();   // all reads of xbuf/ws done before overwrite
#pragma unroll
    for (int j = 0; j < NJ; ++j) {
        const int o2 = (lane + (j << 5)) << 1;
#pragma unroll
        for (int i = 0; i < 8; ++i) {
            float lo, hi;
            unpack2(acc[i][j], lo, hi);
            float2 r;
            r.x = fmaxf(lo, 0.0f);
            r.y = fmaxf(hi, 0.0f);
            *reinterpret_cast<float2*>(xbuf + (mb + i) * 256 + o2) = r;   // 8B lane-consecutive
        }
    }
    __syncthreads();
}

__global__ void __launch_bounds__(THREADS, 2) nerf_fused(
    const float* __restrict__ sp,   const float* __restrict__ dirs,
    const float* __restrict__ Wx0,  const float* __restrict__ bx0,
    const float* __restrict__ Wx1,  const float* __restrict__ bx1,
    const float* __restrict__ Wx2,  const float* __restrict__ bx2,
    const float* __restrict__ Wx3,  const float* __restrict__ bx3,
    const float* __restrict__ Wx4,  const float* __restrict__ bx4,
    const float* __restrict__ Wx5,  const float* __restrict__ bx5,
    const float* __restrict__ Wx6,  const float* __restrict__ bx6,
    const float* __restrict__ Wx7,  const float* __restrict__ bx7,
    const float* __restrict__ Wd0,  const float* __restrict__ bd0,
    const float* __restrict__ Wden, const float* __restrict__ bden,
    const float* __restrict__ Wfeat,const float* __restrict__ bfeat,
    const float* __restrict__ Wrgb, const float* __restrict__ brgb,
    float* __restrict__ out)
{
    extern __shared__ float sm[];
    float* xbuf = sm + XBUF_OFF;
    float* emb  = sm + EMB_OFF;
    float* ws   = sm + WS_OFF;
    float* dens = sm + DENS_OFF;
    float* embd = sm + EMBD_OFF;

    const int tid  = threadIdx.x;
    const int lane = tid & 31;
    const int warp = tid >> 5;
    const int p0   = blockIdx.x << 6;   // one ray (64 samples) per block

    // ---- Phase 0: xyz harmonic embedding [sin(30), cos(30), xyz(3), pad0] ----
    if (tid < 64) {
        const float* pp = sp + (size_t)(p0 + tid) * 3;
        float* e = emb + tid * 64;
#pragma unroll
        for (int d = 0; d < 3; ++d) {
            float x = pp[d];
            float f = 1.0f;
#pragma unroll
            for (int h = 0; h < 10; ++h) {
                float s, c;
                sincosf(x * f, &s, &c);
                e[d * 10 + h]      = s;
                e[30 + d * 10 + h] = c;
                f *= 2.0f;
            }
            e[60 + d] = x;
        }
        e[63] = 0.0f;
    }
    // gemm_layer's loop-top __syncthreads orders phase 0 vs first compute

    gemm_layer<4>(Wx0, bx0,  63,  8, 0,  xbuf, emb, ws);   // 63->256 (from emb)
    gemm_layer<4>(Wx1, bx1, 256, 32, 32, xbuf, emb, ws);
    gemm_layer<4>(Wx2, bx2, 256, 32, 32, xbuf, emb, ws);
    gemm_layer<4>(Wx3, bx3, 256, 32, 32, xbuf, emb, ws);
    gemm_layer<4>(Wx4, bx4, 319, 40, 32, xbuf, emb, ws);   // skip: [h(256), emb_x(63)]
    gemm_layer<4>(Wx5, bx5, 256, 32, 32, xbuf, emb, ws);
    gemm_layer<4>(Wx6, bx6, 256, 32, 32, xbuf, emb, ws);
    gemm_layer<4>(Wx7, bx7, 256, 32, 32, xbuf, emb, ws);

    // ---- density head (reads xbuf before feat overwrites it) ----
    {
        const float bd = __ldg(bden);
#pragma unroll 1
        for (int it = 0; it < 8; ++it) {
            int m = warp + (it << 3);
            float s = 0.0f;
#pragma unroll
            for (int kk = 0; kk < 8; ++kk) {
                int k = lane + (kk << 5);
                s += xbuf[m * 256 + k] * __ldg(Wden + k);
            }
#pragma unroll
            for (int off = 16; off > 0; off >>= 1) s += __shfl_xor_sync(0xffffffffu, s, off);
            if (lane == 0) dens[m] = fmaxf(s + bd, 0.0f);
        }
    }
    __syncthreads();

    gemm_layer<4>(Wfeat, bfeat, 256, 32, 32, xbuf, emb, ws);

    // ---- direction embedding [sin(12), cos(12), dir(3), pad0] -> emb cols 0..31 ----
    if (tid < 32) {
        float v = 0.0f;
        if (tid < 12) {
            float x = __ldg(dirs + blockIdx.x * 3 + (tid >> 2));
            v = sinf(x * (float)(1 << (tid & 3)));
        } else if (tid < 24) {
            int kk = tid - 12;
            float x = __ldg(dirs + blockIdx.x * 3 + (kk >> 2));
            v = cosf(x * (float)(1 << (kk & 3)));
        } else if (tid < 27) {
            v = __ldg(dirs + blockIdx.x * 3 + (tid - 24));
        }
        embd[tid] = v;
    }
    __syncthreads();
    for (int idx = tid; idx < 64 * 32; idx += THREADS)
        emb[(idx >> 5) * 64 + (idx & 31)] = embd[idx & 31];

    gemm_layer<2>(Wd0, bd0, 283, 36, 32, xbuf, emb, ws);   // [feat(256), emb_d(27)] -> 128

    // ---- rgb head + output ----
    {
#pragma unroll 1
        for (int it = 0; it < 8; ++it) {
            int m = warp + (it << 3);
            float s0 = 0.0f, s1 = 0.0f, s2 = 0.0f;
#pragma unroll
            for (int kk = 0; kk < 4; ++kk) {
                int k = lane + (kk << 5);
                float h = xbuf[m * 256 + k];
                s0 += h * __ldg(Wrgb + k);
                s1 += h * __ldg(Wrgb + 128 + k);
                s2 += h * __ldg(Wrgb + 256 + k);
            }
#pragma unroll
            for (int off = 16; off > 0; off >>= 1) {
                s0 += __shfl_xor_sync(0xffffffffu, s0, off);
                s1 += __shfl_xor_sync(0xffffffffu, s1, off);
                s2 += __shfl_xor_sync(0xffffffffu, s2, off);
            }
            if (lane == 0) {
                float* op = out + (size_t)(p0 + m) * 4;
                op[0] = dens[m];
                op[1] = 1.0f / (1.0f + expf(-(s0 + __ldg(brgb))));
                op[2] = 1.0f / (1.0f + expf(-(s1 + __ldg(brgb + 1))));
                op[3] = 1.0f / (1.0f + expf(-(s2 + __ldg(brgb + 2))));
            }
        }
    }
}

extern "C" void kernel_launch(void* const* d_in, const int* in_sizes, int n_in,
                              void* d_out, int out_size) {
    (void)in_sizes; (void)n_in; (void)out_size;
    cudaFuncSetAttribute(nerf_fused, cudaFuncAttributeMaxDynamicSharedMemorySize, SMEM_BYTES);
    nerf_fused<<<4096, THREADS, SMEM_BYTES>>>(
        (const float*)d_in[0],  (const float*)d_in[1],
        (const float*)d_in[2],  (const float*)d_in[3],
        (const float*)d_in[4],  (const float*)d_in[5],
        (const float*)d_in[6],  (const float*)d_in[7],
        (const float*)d_in[8],  (const float*)d_in[9],
        (const float*)d_in[10], (const float*)d_in[11],
        (const float*)d_in[12], (const float*)d_in[13],
        (const float*)d_in[14], (const float*)d_in[15],
        (const float*)d_in[16], (const float*)d_in[17],
        (const float*)d_in[18], (const float*)d_in[19],
        (const float*)d_in[20], (const float*)d_in[21],
        (const float*)d_in[22], (const float*)d_in[23],
        (const float*)d_in[24], (const float*)d_in[25],
        (float*)d_out);
}

// round 9
// speedup vs baseline: 3.6737x; 2.2588x over previous
#include <cuda_runtime.h>
#include <cuda_bf16.h>
#include <math.h>
#include <stdint.h>

#define THREADS 256
#define GRID    4096

// ---------------- weight images (bf16, K zero-padded), hi/lo ----------------
#define IOFF_L0   0u
#define IOFF_L1   16384u
#define IOFF_L2   81920u
#define IOFF_L3   147456u
#define IOFF_L4   212992u
#define IOFF_L5   294912u
#define IOFF_L6   360448u
#define IOFF_L7   425984u
#define IOFF_FT   491520u
#define IOFF_DIR  557056u
#define IMG_ELEMS 593920u

__device__ __align__(16) __nv_bfloat16 g_whi[IMG_ELEMS];
__device__ __align__(16) __nv_bfloat16 g_wlo[IMG_ELEMS];

// ---------------- smem layout (bytes) ----------------
#define SM_ACTH  0        // [64][264] bf16 activations hi (stride 264 el = 528B, conflict-free)
#define SM_ACTL  33792
#define SM_WBUF  67584    // 2 bufs x (hi 20480 + lo 20480): [256n][40 el stride] per 32-k chunk
#define SM_EMBXH 149504   // [64][72] bf16 (xyz emb hi); reused for dir emb (stride 40)
#define SM_EMBXL 158720
#define SM_BIAS  167936   // 256 f32
#define SM_WDEN  168960   // 256 f32
#define SM_WRGB  169984   // 384 f32
#define SM_DENSP 171520   // 4x64 f32 (also reused as 32-float dir scratch)
#define SM_RGBP  172544   // 12x64 f32
#define SM_DENS  175616   // 64 f32
#define SMEM_BYTES 175872

// ---------------- low-level helpers ----------------
__device__ __forceinline__ uint32_t s2u(const void* p) {
    uint32_t a;
    asm("{ .reg .u64 t; cvta.to.shared.u64 t, %1; cvt.u32.u64 %0, t; }" : "=r"(a) : "l"(p));
    return a;
}
__device__ __forceinline__ void ldsm4(uint32_t* r, uint32_t a) {
    asm volatile("ldmatrix.sync.aligned.m8n8.x4.shared.b16 {%0,%1,%2,%3}, [%4];"
        : "=r"(r[0]), "=r"(r[1]), "=r"(r[2]), "=r"(r[3]) : "r"(a));
}
__device__ __forceinline__ void mma_bf16(float* c, const uint32_t* a, const uint32_t* b) {
    asm volatile("mma.sync.aligned.m16n8k16.row.col.f32.bf16.bf16.f32 "
        "{%0,%1,%2,%3},{%4,%5,%6,%7},{%8,%9},{%0,%1,%2,%3};"
        : "+f"(c[0]), "+f"(c[1]), "+f"(c[2]), "+f"(c[3])
        : "r"(a[0]), "r"(a[1]), "r"(a[2]), "r"(a[3]), "r"(b[0]), "r"(b[1]));
}
__device__ __forceinline__ void cpa16(uint32_t dst, const void* src) {
    asm volatile("cp.async.cg.shared.global [%0], [%1], 16;" :: "r"(dst), "l"(src));
}
#define CP_COMMIT() asm volatile("cp.async.commit_group;" ::: "memory")
#define CP_WAIT0()  asm volatile("cp.async.wait_group 0;" ::: "memory")

__device__ __forceinline__ void split2(float x, float y, uint32_t& h, uint32_t& l) {
    __nv_bfloat16 hx = __float2bfloat16(x);
    __nv_bfloat16 hy = __float2bfloat16(y);
    __nv_bfloat16 lx = __float2bfloat16(x - __bfloat162float(hx));
    __nv_bfloat16 ly = __float2bfloat16(y - __bfloat162float(hy));
    h = ((uint32_t)__bfloat16_as_ushort(hy) << 16) | __bfloat16_as_ushort(hx);
    l = ((uint32_t)__bfloat16_as_ushort(ly) << 16) | __bfloat16_as_ushort(lx);
}

// ---------------- weight prep: fp32 -> bf16 hi/lo, K zero-padded ----------------
__global__ void prep_weights(const float* __restrict__ W, int in_dim, int Kpad,
                             int Nrows, unsigned off) {
    int idx = blockIdx.x * blockDim.x + threadIdx.x;
    if (idx >= Nrows * Kpad) return;
    int o = idx / Kpad, k = idx - o * Kpad;
    float w = (k < in_dim) ? __ldg(W + (size_t)o * in_dim + k) : 0.0f;
    __nv_bfloat16 h = __float2bfloat16(w);
    g_whi[off + idx] = h;
    g_wlo[off + idx] = __float2bfloat16(w - __bfloat162float(h));
}

// ---------------- stage one 32-k weight chunk (hi+lo) via cp.async ----------------
__device__ __forceinline__ void stage(uint32_t wb, unsigned img_off,
                                      int Kpad, int Nrows, int k0, int tid) {
    int total = Nrows * 4;                       // 16B units per image (32k * 2B / 16)
#pragma unroll 1
    for (int idx = tid; idx < total * 2; idx += THREADS) {
        int im = idx >= total;
        int rem = im ? idx - total : idx;
        int n = rem >> 2, seg = rem & 3;
        const __nv_bfloat16* src = (im ? g_wlo : g_whi) + img_off + (size_t)n * Kpad + k0 + seg * 8;
        cpa16(wb + (im ? 20480 : 0) + (n * 40 + seg * 8) * 2, src);
    }
}

// ---------------- one layer (noinline: 3 instantiations share code) ----------------
// N = NB*32 outputs. Warp w: m-block (w&1)*32, n-block (w>>2? no: w>>1)*(NB*8).
// EPI: 0 = relu->act writeback; 1 = + density partials; 2 = rgb partials only (no writeback)
template<int NB, int EPI>
__device__ __noinline__ void layer(char* smem, uint32_t smb,
                                   unsigned img_off, const float* __restrict__ bias_g,
                                   int Kpad, int nc, int xc,
                                   uint32_t embh, uint32_t embl, int estr) {
    const int tid  = threadIdx.x;
    const int lane = tid & 31;
    const int w    = tid >> 5;
    const int N    = NB * 32;
    const int mb   = (w & 1) * 32;
    const int nb   = (w >> 1) * (NB * 8);

    float acc[2][NB][4];
#pragma unroll
    for (int i = 0; i < 2; ++i)
#pragma unroll
        for (int j = 0; j < NB; ++j)
#pragma unroll
            for (int r = 0; r < 4; ++r) acc[i][j][r] = 0.0f;

    if (tid < N) ((float*)(smem + SM_BIAS))[tid] = __ldg(bias_g + tid);
    stage(smb + SM_WBUF, img_off, Kpad, N, 0, tid);
    CP_COMMIT();

    const int m_off  = (lane & 7) + ((lane >> 3) & 1) * 8;
    const int ak_off = (lane >> 4) * 8;
    const int n_off  = (lane & 7) + ((lane >> 4) << 3);
    const int bk_off = ((lane >> 3) & 1) * 8;

#pragma unroll 1
    for (int c = 0; c < nc; ++c) {
        CP_WAIT0();
        __syncthreads();            // chunk c landed; all warps past mma(c-1)
        if (c + 1 < nc) {
            stage(smb + SM_WBUF + ((c + 1) & 1) * 40960, img_off, Kpad, N, (c + 1) * 32, tid);
            CP_COMMIT();
        }
        uint32_t ah, al; int astr, koff;
        if (c < xc) { ah = smb + SM_ACTH; al = smb + SM_ACTL; astr = 264; koff = c * 32; }
        else        { ah = embh;          al = embl;          astr = estr; koff = (c - xc) * 32; }
        uint32_t wb = smb + SM_WBUF + (c & 1) * 40960;

#pragma unroll
        for (int ks = 0; ks < 2; ++ks) {
            int kk = koff + ks * 16;
            uint32_t Ah0[4], Ah1[4], Al0[4], Al1[4];
            uint32_t aa = ((mb + m_off) * astr + kk + ak_off) * 2;
            ldsm4(Ah0, ah + aa);
            ldsm4(Ah1, ah + aa + 32 * astr);     // +16 rows * stride * 2B
            ldsm4(Al0, al + aa);
            ldsm4(Al1, al + aa + 32 * astr);
#pragma unroll
            for (int jp = 0; jp < NB / 2; ++jp) {
                uint32_t Bh[4], Bl[4];
                uint32_t ba = wb + ((nb + jp * 16 + n_off) * 40 + ks * 16 + bk_off) * 2;
                ldsm4(Bh, ba);
                ldsm4(Bl, ba + 20480);
#pragma unroll
                for (int i = 0; i < 2; ++i) {
                    const uint32_t* Ahx = i ? Ah1 : Ah0;
                    const uint32_t* Alx = i ? Al1 : Al0;
#pragma unroll
                    for (int jj = 0; jj < 2; ++jj) {
                        float* cc = acc[i][jp * 2 + jj];
                        mma_bf16(cc, Ahx, &Bh[jj * 2]);
                        mma_bf16(cc, Alx, &Bh[jj * 2]);
                        mma_bf16(cc, Ahx, &Bl[jj * 2]);
                    }
                }
            }
        }
    }
    __syncthreads();                 // all act reads done before writeback

    // ---- epilogue ----
    const float* bias_s = (const float*)(smem + SM_BIAS);
    float ds[4] = {0, 0, 0, 0};
    float pr[12] = {0, 0, 0, 0, 0, 0, 0, 0, 0, 0, 0, 0};
#pragma unroll
    for (int i = 0; i < 2; ++i)
#pragma unroll
    for (int j = 0; j < NB; ++j) {
        int n = nb + j * 8 + (lane & 3) * 2;
        float bx = bias_s[n], by = bias_s[n + 1];
        float r00 = fmaxf(acc[i][j][0] + bx, 0.0f);
        float r01 = fmaxf(acc[i][j][1] + by, 0.0f);
        float r10 = fmaxf(acc[i][j][2] + bx, 0.0f);
        float r11 = fmaxf(acc[i][j][3] + by, 0.0f);
        if (EPI != 2) {
            int m0 = mb + i * 16 + (lane >> 2);
            uint32_t h, l;
            split2(r00, r01, h, l);
            *(uint32_t*)(smem + SM_ACTH + (m0 * 264 + n) * 2) = h;
            *(uint32_t*)(smem + SM_ACTL + (m0 * 264 + n) * 2) = l;
            split2(r10, r11, h, l);
            *(uint32_t*)(smem + SM_ACTH + ((m0 + 8) * 264 + n) * 2) = h;
            *(uint32_t*)(smem + SM_ACTL + ((m0 + 8) * 264 + n) * 2) = l;
        }
        if (EPI == 1) {
            const float* wd = (const float*)(smem + SM_WDEN);
            ds[i * 2 + 0] += r00 * wd[n] + r01 * wd[n + 1];
            ds[i * 2 + 1] += r10 * wd[n] + r11 * wd[n + 1];
        }
        if (EPI == 2) {
            const float* wr = (const float*)(smem + SM_WRGB);
#pragma unroll
            for (int ch = 0; ch < 3; ++ch) {
                pr[(i * 2 + 0) * 3 + ch] += r00 * wr[ch * 128 + n] + r01 * wr[ch * 128 + n + 1];
                pr[(i * 2 + 1) * 3 + ch] += r10 * wr[ch * 128 + n] + r11 * wr[ch * 128 + n + 1];
            }
        }
    }
    if (EPI == 1) {
#pragma unroll
        for (int q = 0; q < 4; ++q) {
            ds[q] += __shfl_xor_sync(0xffffffffu, ds[q], 1);
            ds[q] += __shfl_xor_sync(0xffffffffu, ds[q], 2);
        }
        if ((lane & 3) == 0) {
            float* dp = (float*)(smem + SM_DENSP);
#pragma unroll
            for (int i = 0; i < 2; ++i)
#pragma unroll
            for (int h2 = 0; h2 < 2; ++h2)
                dp[(w >> 1) * 64 + mb + i * 16 + h2 * 8 + (lane >> 2)] = ds[i * 2 + h2];
        }
    }
    if (EPI == 2) {
#pragma unroll
        for (int q = 0; q < 12; ++q) {
            pr[q] += __shfl_xor_sync(0xffffffffu, pr[q], 1);
            pr[q] += __shfl_xor_sync(0xffffffffu, pr[q], 2);
        }
        if ((lane & 3) == 0) {
            float* rp = (float*)(smem + SM_RGBP);
#pragma unroll
            for (int i = 0; i < 2; ++i)
#pragma unroll
            for (int h2 = 0; h2 < 2; ++h2)
#pragma unroll
            for (int ch = 0; ch < 3; ++ch)
                rp[(ch * 4 + (w >> 1)) * 64 + mb + i * 16 + h2 * 8 + (lane >> 2)]
                    = pr[(i * 2 + h2) * 3 + ch];
        }
    }
    __syncthreads();
}

// ---------------- main fused kernel ----------------
__global__ void __launch_bounds__(THREADS, 1) nerf_hmma(
    const float* __restrict__ sp,   const float* __restrict__ dirs,
    const float* __restrict__ bx0,  const float* __restrict__ bx1,
    const float* __restrict__ bx2,  const float* __restrict__ bx3,
    const float* __restrict__ bx4,  const float* __restrict__ bx5,
    const float* __restrict__ bx6,  const float* __restrict__ bx7,
    const float* __restrict__ bd0,  const float* __restrict__ bden,
    const float* __restrict__ bfeat,const float* __restrict__ brgb,
    const float* __restrict__ Wden, const float* __restrict__ Wrgb,
    float* __restrict__ out)
{
    extern __shared__ char smem[];
    uint32_t smb = s2u(smem);
    const int tid = threadIdx.x;
    const int p0  = blockIdx.x << 6;

    // xyz harmonic embedding -> bf16 hi/lo tiles [64][72]
    if (tid < 64) {
        float e[64];
        const float* pp = sp + (size_t)(p0 + tid) * 3;
#pragma unroll
        for (int d = 0; d < 3; ++d) {
            float x = pp[d], f = 1.0f;
#pragma unroll
            for (int h = 0; h < 10; ++h) {
                float s, c;
                sincosf(x * f, &s, &c);
                e[d * 10 + h] = s;
                e[30 + d * 10 + h] = c;
                f *= 2.0f;
            }
            e[60 + d] = x;
        }
        e[63] = 0.0f;
#pragma unroll
        for (int k = 0; k < 64; ++k) {
            __nv_bfloat16 h = __float2bfloat16(e[k]);
            __nv_bfloat16 l = __float2bfloat16(e[k] - __bfloat162float(h));
            *(__nv_bfloat16*)(smem + SM_EMBXH + (tid * 72 + k) * 2) = h;
            *(__nv_bfloat16*)(smem + SM_EMBXL + (tid * 72 + k) * 2) = l;
        }
    }
    if (tid < 256) ((float*)(smem + SM_WDEN))[tid] = __ldg(Wden + tid);
    if (tid < 256) ((float*)(smem + SM_WRGB))[tid] = __ldg(Wrgb + tid);
    if (tid < 128) ((float*)(smem + SM_WRGB))[256 + tid] = __ldg(Wrgb + 256 + tid);
    // first layer's CP_WAIT+__syncthreads orders the above before any read

    uint32_t exh = smb + SM_EMBXH, exl = smb + SM_EMBXL;

    layer<8, 0>(smem, smb, IOFF_L0, bx0,  64,  2, 0, exh, exl, 72);
    layer<8, 0>(smem, smb, IOFF_L1, bx1, 256,  8, 8, exh, exl, 72);
    layer<8, 0>(smem, smb, IOFF_L2, bx2, 256,  8, 8, exh, exl, 72);
    layer<8, 0>(smem, smb, IOFF_L3, bx3, 256,  8, 8, exh, exl, 72);
    layer<8, 0>(smem, smb, IOFF_L4, bx4, 320, 10, 8, exh, exl, 72);   // skip concat
    layer<8, 0>(smem, smb, IOFF_L5, bx5, 256,  8, 8, exh, exl, 72);
    layer<8, 0>(smem, smb, IOFF_L6, bx6, 256,  8, 8, exh, exl, 72);
    layer<8, 1>(smem, smb, IOFF_L7, bx7, 256,  8, 8, exh, exl, 72);   // + density partials

    if (tid < 64) {
        const float* dp = (const float*)(smem + SM_DENSP);
        float s = dp[tid] + dp[64 + tid] + dp[128 + tid] + dp[192 + tid] + __ldg(bden);
        ((float*)(smem + SM_DENS))[tid] = fmaxf(s, 0.0f);
    }

    layer<8, 0>(smem, smb, IOFF_FT, bfeat, 256, 8, 8, exh, exl, 72);

    // direction embedding (one ray per CTA) -> [64][40] tiles in embx space
    if (tid < 32) {
        float v = 0.0f;
        if (tid < 12) {
            float x = __ldg(dirs + blockIdx.x * 3 + (tid >> 2));
            v = sinf(x * (float)(1 << (tid & 3)));
        } else if (tid < 24) {
            int kk = tid - 12;
            float x = __ldg(dirs + blockIdx.x * 3 + (kk >> 2));
            v = cosf(x * (float)(1 << (kk & 3)));
        } else if (tid < 27) {
            v = __ldg(dirs + blockIdx.x * 3 + (tid - 24));
        }
        ((float*)(smem + SM_DENSP))[tid] = v;    // densp free now (dens extracted)
    }
    __syncthreads();
    {
        int row = tid >> 2;
        int k0 = (tid & 3) * 8;
        const float* sc = (const float*)(smem + SM_DENSP);
#pragma unroll
        for (int e = 0; e < 8; ++e) {
            float v = sc[k0 + e];
            __nv_bfloat16 h = __float2bfloat16(v);
            __nv_bfloat16 l = __float2bfloat16(v - __bfloat162float(h));
            *(__nv_bfloat16*)(smem + SM_EMBXH + (row * 40 + k0 + e) * 2) = h;
            *(__nv_bfloat16*)(smem + SM_EMBXL + (row * 40 + k0 + e) * 2) = l;
        }
    }
    __syncthreads();

    layer<4, 2>(smem, smb, IOFF_DIR, bd0, 288, 9, 8, exh, exl, 40);   // rgb partials

    if (tid < 64) {
        const float* rp = (const float*)(smem + SM_RGBP);
        float* op = out + (size_t)(p0 + tid) * 4;
        op[0] = ((const float*)(smem + SM_DENS))[tid];
#pragma unroll
        for (int ch = 0; ch < 3; ++ch) {
            float s = rp[(ch * 4 + 0) * 64 + tid] + rp[(ch * 4 + 1) * 64 + tid]
                    + rp[(ch * 4 + 2) * 64 + tid] + rp[(ch * 4 + 3) * 64 + tid]
                    + __ldg(brgb + ch);
            op[1 + ch] = 1.0f / (1.0f + expf(-s));
        }
    }
}

extern "C" void kernel_launch(void* const* d_in, const int* in_sizes, int n_in,
                              void* d_out, int out_size) {
    (void)in_sizes; (void)n_in; (void)out_size;
    const unsigned ioff[10] = {IOFF_L0, IOFF_L1, IOFF_L2, IOFF_L3, IOFF_L4,
                               IOFF_L5, IOFF_L6, IOFF_L7, IOFF_FT, IOFF_DIR};
    const int ind[10]  = {63, 256, 256, 256, 319, 256, 256, 256, 256, 283};
    const int kpad[10] = {64, 256, 256, 256, 320, 256, 256, 256, 256, 288};
    const int nrow[10] = {256, 256, 256, 256, 256, 256, 256, 256, 256, 128};
    const float* Wsrc[10] = {(const float*)d_in[2],  (const float*)d_in[4],
                             (const float*)d_in[6],  (const float*)d_in[8],
                             (const float*)d_in[10], (const float*)d_in[12],
                             (const float*)d_in[14], (const float*)d_in[16],
                             (const float*)d_in[22],   // Wfeat
                             (const float*)d_in[18]};  // Wd0
    for (int l = 0; l < 10; ++l) {
        int tot = nrow[l] * kpad[l];
        prep_weights<<<(tot + 255) / 256, 256>>>(Wsrc[l], ind[l], kpad[l], nrow[l], ioff[l]);
    }

    cudaFuncSetAttribute(nerf_hmma, cudaFuncAttributeMaxDynamicSharedMemorySize, SMEM_BYTES);
    nerf_hmma<<<GRID, THREADS, SMEM_BYTES>>>(
        (const float*)d_in[0],  (const float*)d_in[1],
        (const float*)d_in[3],  (const float*)d_in[5],
        (const float*)d_in[7],  (const float*)d_in[9],
        (const float*)d_in[11], (const float*)d_in[13],
        (const float*)d_in[15], (const float*)d_in[17],
        (const float*)d_in[19], (const float*)d_in[21],
        (const float*)d_in[23], (const float*)d_in[25],
        (const float*)d_in[20],   // Wden
        (const float*)d_in[24],   // Wrgb
        (float*)d_out);
}

// round 10
// speedup vs baseline: 6.3204x; 1.7204x over previous
#include <cuda_runtime.h>
#include <cuda_fp16.h>
#include <math.h>
#include <stdint.h>

#define THREADS 256
#define GRID    2048
#define NSAMP   128

// ---------------- weight images (fp16 hi/lo, K zero-padded) ----------------
#define IOFF_L0   0u
#define IOFF_L1   16384u
#define IOFF_L2   81920u
#define IOFF_L3   147456u
#define IOFF_L4   212992u
#define IOFF_L5   294912u
#define IOFF_L6   360448u
#define IOFF_L7   425984u
#define IOFF_FT   491520u
#define IOFF_DIR  557056u
#define IMG_ELEMS 593920u

__device__ __align__(16) __half g_whi[IMG_ELEMS];
__device__ __align__(16) __half g_wlo[IMG_ELEMS];

// ---------------- smem layout (bytes) ----------------
#define SM_ACT   0        // [128][264] fp16 activations (stride 528B = 33x16B, conflict-free)
#define SM_WBUF  67584    // 2 bufs x (hi 20480 + lo 20480): [256n][40 el] per 32-k chunk
#define SM_EMB   149504   // [128][72] fp16 xyz emb; reused as [128][40] dir emb
#define SM_BIAS  167936   // 256 f32
#define SM_WDEN  168960   // 256 f32
#define SM_WRGB  169984   // 384 f32
#define SM_DENSP 171520   // 4x128 f32
#define SM_RGBP  173568   // 12x128 f32
#define SM_DENS  179712   // 128 f32
#define SM_DIRS  180224   // 2x32 f32
#define SMEM_BYTES 180480

// ---------------- low-level helpers ----------------
__device__ __forceinline__ uint32_t s2u(const void* p) {
    uint32_t a;
    asm("{ .reg .u64 t; cvta.to.shared.u64 t, %1; cvt.u32.u64 %0, t; }" : "=r"(a) : "l"(p));
    return a;
}
__device__ __forceinline__ void ldsm4(uint32_t* r, uint32_t a) {
    asm volatile("ldmatrix.sync.aligned.m8n8.x4.shared.b16 {%0,%1,%2,%3}, [%4];"
        : "=r"(r[0]), "=r"(r[1]), "=r"(r[2]), "=r"(r[3]) : "r"(a));
}
__device__ __forceinline__ void mma_f16(float* c, const uint32_t* a, const uint32_t* b) {
    asm volatile("mma.sync.aligned.m16n8k16.row.col.f32.f16.f16.f32 "
        "{%0,%1,%2,%3},{%4,%5,%6,%7},{%8,%9},{%0,%1,%2,%3};"
        : "+f"(c[0]), "+f"(c[1]), "+f"(c[2]), "+f"(c[3])
        : "r"(a[0]), "r"(a[1]), "r"(a[2]), "r"(a[3]), "r"(b[0]), "r"(b[1]));
}
__device__ __forceinline__ void cpa16(uint32_t dst, const void* src) {
    asm volatile("cp.async.cg.shared.global [%0], [%1], 16;" :: "r"(dst), "l"(src));
}
#define CP_COMMIT() asm volatile("cp.async.commit_group;" ::: "memory")
#define CP_WAIT0()  asm volatile("cp.async.wait_group 0;" ::: "memory")

__device__ __forceinline__ uint32_t packh(float x, float y) {
    __half2 h = __floats2half2_rn(x, y);
    return *reinterpret_cast<uint32_t*>(&h);
}

// ---------------- fused weight prep: fp32 -> fp16 hi/lo, one launch ----------------
__global__ void prep_all(const float* __restrict__ W0, const float* __restrict__ W1,
                         const float* __restrict__ W2, const float* __restrict__ W3,
                         const float* __restrict__ W4, const float* __restrict__ W5,
                         const float* __restrict__ W6, const float* __restrict__ W7,
                         const float* __restrict__ W8, const float* __restrict__ W9) {
    unsigned idx = blockIdx.x * blockDim.x + threadIdx.x;
    if (idx >= IMG_ELEMS) return;
    unsigned off; const float* W; int ind, kpad;
    if      (idx < IOFF_L1)  { off = IOFF_L0;  W = W0; ind = 63;  kpad = 64;  }
    else if (idx < IOFF_L2)  { off = IOFF_L1;  W = W1; ind = 256; kpad = 256; }
    else if (idx < IOFF_L3)  { off = IOFF_L2;  W = W2; ind = 256; kpad = 256; }
    else if (idx < IOFF_L4)  { off = IOFF_L3;  W = W3; ind = 256; kpad = 256; }
    else if (idx < IOFF_L5)  { off = IOFF_L4;  W = W4; ind = 319; kpad = 320; }
    else if (idx < IOFF_L6)  { off = IOFF_L5;  W = W5; ind = 256; kpad = 256; }
    else if (idx < IOFF_L7)  { off = IOFF_L6;  W = W6; ind = 256; kpad = 256; }
    else if (idx < IOFF_FT)  { off = IOFF_L7;  W = W7; ind = 256; kpad = 256; }
    else if (idx < IOFF_DIR) { off = IOFF_FT;  W = W8; ind = 256; kpad = 256; }
    else                     { off = IOFF_DIR; W = W9; ind = 283; kpad = 288; }
    unsigned r = idx - off;
    int o = r / kpad, k = r - o * kpad;
    float w = (k < ind) ? __ldg(W + (size_t)o * ind + k) : 0.0f;
    __half h = __float2half_rn(w);
    g_whi[idx] = h;
    g_wlo[idx] = __float2half_rn(w - __half2float(h));
}

// ---------------- stage one 32-k weight chunk (hi+lo) via cp.async ----------------
__device__ __forceinline__ void stage(uint32_t wb, unsigned img_off,
                                      int Kpad, int Nrows, int k0, int tid) {
    int total = Nrows * 4;                       // 16B units per image
#pragma unroll 1
    for (int idx = tid; idx < total * 2; idx += THREADS) {
        int im = idx >= total;
        int rem = im ? idx - total : idx;
        int n = rem >> 2, seg = rem & 3;
        const __half* src = (im ? g_wlo : g_whi) + img_off + (size_t)n * Kpad + k0 + seg * 8;
        cpa16(wb + (im ? 20480 : 0) + (n * 40 + seg * 8) * 2, src);
    }
}

// ---------------- one layer ----------------
// M=128: warp mb=(w&1)*64 (4 m16 tiles). N=NB*32: warp nb=(w>>1)*NB*8.
// EPI: 0 = relu->act; 1 = relu->act + density partials; 2 = rgb partials only
template<int NB, int EPI>
__device__ __noinline__ void layer(char* smem, uint32_t smb,
                                   unsigned img_off, const float* __restrict__ bias_g,
                                   int Kpad, int nc, int xc, int estr) {
    const int tid  = threadIdx.x;
    const int lane = tid & 31;
    const int w    = tid >> 5;
    const int N    = NB * 32;
    const int mb   = (w & 1) * 64;
    const int nb   = (w >> 1) * (NB * 8);

    float acc[4][NB][4];
#pragma unroll
    for (int i = 0; i < 4; ++i)
#pragma unroll
        for (int j = 0; j < NB; ++j)
#pragma unroll
            for (int r = 0; r < 4; ++r) acc[i][j][r] = 0.0f;

    if (tid < N) ((float*)(smem + SM_BIAS))[tid] = __ldg(bias_g + tid);
    stage(smb + SM_WBUF, img_off, Kpad, N, 0, tid);
    CP_COMMIT();

    const int m_off  = (lane & 7) + ((lane >> 3) & 1) * 8;
    const int ak_off = (lane >> 4) * 8;
    const int n_off  = (lane & 7) + ((lane >> 4) << 3);
    const int bk_off = ((lane >> 3) & 1) * 8;

#pragma unroll 1
    for (int c = 0; c < nc; ++c) {
        CP_WAIT0();
        __syncthreads();
        if (c + 1 < nc) {
            stage(smb + SM_WBUF + ((c + 1) & 1) * 40960, img_off, Kpad, N, (c + 1) * 32, tid);
            CP_COMMIT();
        }
        uint32_t ab; int astr, koff;
        if (c < xc) { ab = smb + SM_ACT; astr = 264;  koff = c * 32; }
        else        { ab = smb + SM_EMB; astr = estr; koff = (c - xc) * 32; }
        uint32_t wb = smb + SM_WBUF + (c & 1) * 40960;

#pragma unroll
        for (int ks = 0; ks < 2; ++ks) {
            int kk = koff + ks * 16;
            uint32_t A[4][4];
#pragma unroll
            for (int i = 0; i < 4; ++i)
                ldsm4(A[i], ab + ((mb + i * 16 + m_off) * astr + kk + ak_off) * 2);
#pragma unroll
            for (int jp = 0; jp < NB / 2; ++jp) {
                uint32_t Bh[4], Bl[4];
                uint32_t ba = wb + ((nb + jp * 16 + n_off) * 40 + ks * 16 + bk_off) * 2;
                ldsm4(Bh, ba);
                ldsm4(Bl, ba + 20480);
#pragma unroll
                for (int i = 0; i < 4; ++i)
#pragma unroll
                    for (int jj = 0; jj < 2; ++jj) {
                        float* cc = acc[i][jp * 2 + jj];
                        mma_f16(cc, A[i], &Bh[jj * 2]);
                        mma_f16(cc, A[i], &Bl[jj * 2]);
                    }
            }
        }
    }
    __syncthreads();

    // ---- epilogue ----
    const float* bias_s = (const float*)(smem + SM_BIAS);
    float ds[8];
    float pr[24];
    if (EPI == 1) {
#pragma unroll
        for (int q = 0; q < 8; ++q) ds[q] = 0.0f;
    }
    if (EPI == 2) {
#pragma unroll
        for (int q = 0; q < 24; ++q) pr[q] = 0.0f;
    }
#pragma unroll
    for (int i = 0; i < 4; ++i)
#pragma unroll
    for (int j = 0; j < NB; ++j) {
        int n = nb + j * 8 + (lane & 3) * 2;
        float bx = bias_s[n], by = bias_s[n + 1];
        float r00 = fmaxf(acc[i][j][0] + bx, 0.0f);
        float r01 = fmaxf(acc[i][j][1] + by, 0.0f);
        float r10 = fmaxf(acc[i][j][2] + bx, 0.0f);
        float r11 = fmaxf(acc[i][j][3] + by, 0.0f);
        if (EPI != 2) {
            int m0 = mb + i * 16 + (lane >> 2);
            *(uint32_t*)(smem + SM_ACT + (m0 * 264 + n) * 2)       = packh(r00, r01);
            *(uint32_t*)(smem + SM_ACT + ((m0 + 8) * 264 + n) * 2) = packh(r10, r11);
        }
        if (EPI == 1) {
            const float* wd = (const float*)(smem + SM_WDEN);
            ds[i * 2 + 0] += r00 * wd[n] + r01 * wd[n + 1];
            ds[i * 2 + 1] += r10 * wd[n] + r11 * wd[n + 1];
        }
        if (EPI == 2) {
            const float* wr = (const float*)(smem + SM_WRGB);
#pragma unroll
            for (int ch = 0; ch < 3; ++ch) {
                pr[(i * 2 + 0) * 3 + ch] += r00 * wr[ch * 128 + n] + r01 * wr[ch * 128 + n + 1];
                pr[(i * 2 + 1) * 3 + ch] += r10 * wr[ch * 128 + n] + r11 * wr[ch * 128 + n + 1];
            }
        }
    }
    if (EPI == 1) {
#pragma unroll
        for (int q = 0; q < 8; ++q) {
            ds[q] += __shfl_xor_sync(0xffffffffu, ds[q], 1);
            ds[q] += __shfl_xor_sync(0xffffffffu, ds[q], 2);
        }
        if ((lane & 3) == 0) {
            float* dp = (float*)(smem + SM_DENSP);
#pragma unroll
            for (int i = 0; i < 4; ++i)
#pragma unroll
            for (int h2 = 0; h2 < 2; ++h2)
                dp[(w >> 1) * 128 + mb + i * 16 + h2 * 8 + (lane >> 2)] = ds[i * 2 + h2];
        }
    }
    if (EPI == 2) {
#pragma unroll
        for (int q = 0; q < 24; ++q) {
            pr[q] += __shfl_xor_sync(0xffffffffu, pr[q], 1);
            pr[q] += __shfl_xor_sync(0xffffffffu, pr[q], 2);
        }
        if ((lane & 3) == 0) {
            float* rp = (float*)(smem + SM_RGBP);
#pragma unroll
            for (int i = 0; i < 4; ++i)
#pragma unroll
            for (int h2 = 0; h2 < 2; ++h2)
#pragma unroll
            for (int ch = 0; ch < 3; ++ch)
                rp[(ch * 4 + (w >> 1)) * 128 + mb + i * 16 + h2 * 8 + (lane >> 2)]
                    = pr[(i * 2 + h2) * 3 + ch];
        }
    }
    __syncthreads();
}

// ---------------- main fused kernel ----------------
__global__ void __launch_bounds__(THREADS, 1) nerf_hmma(
    const float* __restrict__ sp,   const float* __restrict__ dirs,
    const float* __restrict__ bx0,  const float* __restrict__ bx1,
    const float* __restrict__ bx2,  const float* __restrict__ bx3,
    const float* __restrict__ bx4,  const float* __restrict__ bx5,
    const float* __restrict__ bx6,  const float* __restrict__ bx7,
    const float* __restrict__ bd0,  const float* __restrict__ bden,
    const float* __restrict__ bfeat,const float* __restrict__ brgb,
    const float* __restrict__ Wden, const float* __restrict__ Wrgb,
    float* __restrict__ out)
{
    extern __shared__ char smem[];
    uint32_t smb = s2u(smem);
    const int tid = threadIdx.x;
    const int p0  = blockIdx.x * NSAMP;

    // xyz harmonic embedding -> fp16 tile [128][72]
    if (tid < NSAMP) {
        float e[64];
        const float* pp = sp + (size_t)(p0 + tid) * 3;
#pragma unroll
        for (int d = 0; d < 3; ++d) {
            float x = pp[d], f = 1.0f;
#pragma unroll
            for (int h = 0; h < 10; ++h) {
                float s, c;
                sincosf(x * f, &s, &c);
                e[d * 10 + h] = s;
                e[30 + d * 10 + h] = c;
                f *= 2.0f;
            }
            e[60 + d] = x;
        }
        e[63] = 0.0f;
#pragma unroll
        for (int k = 0; k < 32; ++k)
            *(uint32_t*)(smem + SM_EMB + (tid * 72 + k * 2) * 2) = packh(e[2 * k], e[2 * k + 1]);
    }
    if (tid < 256) ((float*)(smem + SM_WDEN))[tid] = __ldg(Wden + tid);
    if (tid < 256) ((float*)(smem + SM_WRGB))[tid] = __ldg(Wrgb + tid);
    if (tid < 128) ((float*)(smem + SM_WRGB))[256 + tid] = __ldg(Wrgb + 256 + tid);
    // first layer's CP_WAIT+__syncthreads orders the above before any read

    layer<8, 0>(smem, smb, IOFF_L0, bx0,  64,  2, 0, 72);
    layer<8, 0>(smem, smb, IOFF_L1, bx1, 256,  8, 8, 72);
    layer<8, 0>(smem, smb, IOFF_L2, bx2, 256,  8, 8, 72);
    layer<8, 0>(smem, smb, IOFF_L3, bx3, 256,  8, 8, 72);
    layer<8, 0>(smem, smb, IOFF_L4, bx4, 320, 10, 8, 72);   // skip concat
    layer<8, 0>(smem, smb, IOFF_L5, bx5, 256,  8, 8, 72);
    layer<8, 0>(smem, smb, IOFF_L6, bx6, 256,  8, 8, 72);
    layer<8, 1>(smem, smb, IOFF_L7, bx7, 256,  8, 8, 72);   // + density partials

    if (tid < NSAMP) {
        const float* dp = (const float*)(smem + SM_DENSP);
        float s = dp[tid] + dp[128 + tid] + dp[256 + tid] + dp[384 + tid] + __ldg(bden);
        ((float*)(smem + SM_DENS))[tid] = fmaxf(s, 0.0f);
    }

    layer<8, 0>(smem, smb, IOFF_FT, bfeat, 256, 8, 8, 72);

    // direction embedding: 2 rays per CTA -> scratch[2][32] -> [128][40] fp16 tile
    if (tid < 64) {
        int ray = tid >> 5, kk = tid & 31;
        float v = 0.0f;
        if (kk < 12) {
            float x = __ldg(dirs + (size_t)(blockIdx.x * 2 + ray) * 3 + (kk >> 2));
            v = sinf(x * (float)(1 << (kk & 3)));
        } else if (kk < 24) {
            int q = kk - 12;
            float x = __ldg(dirs + (size_t)(blockIdx.x * 2 + ray) * 3 + (q >> 2));
            v = cosf(x * (float)(1 << (q & 3)));
        } else if (kk < 27) {
            v = __ldg(dirs + (size_t)(blockIdx.x * 2 + ray) * 3 + (kk - 24));
        }
        ((float*)(smem + SM_DIRS))[tid] = v;
    }
    __syncthreads();
#pragma unroll 1
    for (int idx = tid; idx < NSAMP * 16; idx += THREADS) {
        int row = idx >> 4, k2 = idx & 15;
        const float* sc = (const float*)(smem + SM_DIRS) + (row >> 6) * 32;
        *(uint32_t*)(smem + SM_EMB + (row * 40 + k2 * 2) * 2) = packh(sc[2 * k2], sc[2 * k2 + 1]);
    }
    __syncthreads();

    layer<4, 2>(smem, smb, IOFF_DIR, bd0, 288, 9, 8, 40);   // rgb partials

    if (tid < NSAMP) {
        const float* rp = (const float*)(smem + SM_RGBP);
        float* op = out + (size_t)(p0 + tid) * 4;
        op[0] = ((const float*)(smem + SM_DENS))[tid];
#pragma unroll
        for (int ch = 0; ch < 3; ++ch) {
            float s = rp[(ch * 4 + 0) * 128 + tid] + rp[(ch * 4 + 1) * 128 + tid]
                    + rp[(ch * 4 + 2) * 128 + tid] + rp[(ch * 4 + 3) * 128 + tid]
                    + __ldg(brgb + ch);
            op[1 + ch] = 1.0f / (1.0f + expf(-s));
        }
    }
}

extern "C" void kernel_launch(void* const* d_in, const int* in_sizes, int n_in,
                              void* d_out, int out_size) {
    (void)in_sizes; (void)n_in; (void)out_size;
    prep_all<<<(IMG_ELEMS + 255) / 256, 256>>>(
        (const float*)d_in[2],  (const float*)d_in[4],
        (const float*)d_in[6],  (const float*)d_in[8],
        (const float*)d_in[10], (const float*)d_in[12],
        (const float*)d_in[14], (const float*)d_in[16],
        (const float*)d_in[22],   // Wfeat
        (const float*)d_in[18]);  // Wd0

    cudaFuncSetAttribute(nerf_hmma, cudaFuncAttributeMaxDynamicSharedMemorySize, SMEM_BYTES);
    nerf_hmma<<<GRID, THREADS, SMEM_BYTES>>>(
        (const float*)d_in[0],  (const float*)d_in[1],
        (const float*)d_in[3],  (const float*)d_in[5],
        (const float*)d_in[7],  (const float*)d_in[9],
        (const float*)d_in[11], (const float*)d_in[13],
        (const float*)d_in[15], (const float*)d_in[17],
        (const float*)d_in[19], (const float*)d_in[21],
        (const float*)d_in[23], (const float*)d_in[25],
        (const float*)d_in[20],   // Wden
        (const float*)d_in[24],   // Wrgb
        (float*)d_out);
}

// round 11
// speedup vs baseline: 10.1542x; 1.6066x over previous
#include <cuda_runtime.h>
#include <cuda_fp16.h>
#include <math.h>
#include <stdint.h>

#define THREADS 256
#define GRID    2048
#define NSAMP   128

// ---------------- weight image (fp16, K zero-padded) ----------------
#define IOFF_L0   0u
#define IOFF_L1   16384u
#define IOFF_L2   81920u
#define IOFF_L3   147456u
#define IOFF_L4   212992u
#define IOFF_L5   294912u
#define IOFF_L6   360448u
#define IOFF_L7   425984u
#define IOFF_FT   491520u
#define IOFF_DIR  557056u
#define IMG_ELEMS 593920u

__device__ __align__(16) __half g_w[IMG_ELEMS];

// ---------------- smem layout (bytes) ----------------
#define SM_ACT   0        // [128][264] fp16 activations (stride 528B, ldsm conflict-free)
#define SM_WBUF  67584    // 2 bufs x 20480B: [256n][40 el] per 32-k chunk
#define SM_EMB   108544   // [128][72] fp16 xyz emb; reused as [128][40] dir emb
#define SM_BIAS  126976   // 256 f32
#define SM_WDEN  128000   // 256 f32
#define SM_WRGB  129024   // 384 f32
#define SM_DENSP 130560   // 4x128 f32
#define SM_RGBP  132608   // 12x128 f32
#define SM_DENS  138752   // 128 f32
#define SM_DIRS  139264   // 2x32 f32
#define SMEM_BYTES 139520

// ---------------- low-level helpers ----------------
__device__ __forceinline__ uint32_t s2u(const void* p) {
    uint32_t a;
    asm("{ .reg .u64 t; cvta.to.shared.u64 t, %1; cvt.u32.u64 %0, t; }" : "=r"(a) : "l"(p));
    return a;
}
__device__ __forceinline__ void ldsm4(uint32_t* r, uint32_t a) {
    asm volatile("ldmatrix.sync.aligned.m8n8.x4.shared.b16 {%0,%1,%2,%3}, [%4];"
        : "=r"(r[0]), "=r"(r[1]), "=r"(r[2]), "=r"(r[3]) : "r"(a));
}
__device__ __forceinline__ void mma_f16(float* c, const uint32_t* a, const uint32_t* b) {
    asm volatile("mma.sync.aligned.m16n8k16.row.col.f32.f16.f16.f32 "
        "{%0,%1,%2,%3},{%4,%5,%6,%7},{%8,%9},{%0,%1,%2,%3};"
        : "+f"(c[0]), "+f"(c[1]), "+f"(c[2]), "+f"(c[3])
        : "r"(a[0]), "r"(a[1]), "r"(a[2]), "r"(a[3]), "r"(b[0]), "r"(b[1]));
}
__device__ __forceinline__ void cpa16(uint32_t dst, const void* src) {
    asm volatile("cp.async.cg.shared.global [%0], [%1], 16;" :: "r"(dst), "l"(src));
}
#define CP_COMMIT() asm volatile("cp.async.commit_group;" ::: "memory")
#define CP_WAIT0()  asm volatile("cp.async.wait_group 0;" ::: "memory")

__device__ __forceinline__ uint32_t packh(float x, float y) {
    __half2 h = __floats2half2_rn(x, y);
    return *reinterpret_cast<uint32_t*>(&h);
}

// ---------------- fused weight prep: fp32 -> fp16, one launch ----------------
__global__ void prep_all(const float* __restrict__ W0, const float* __restrict__ W1,
                         const float* __restrict__ W2, const float* __restrict__ W3,
                         const float* __restrict__ W4, const float* __restrict__ W5,
                         const float* __restrict__ W6, const float* __restrict__ W7,
                         const float* __restrict__ W8, const float* __restrict__ W9) {
    unsigned idx = blockIdx.x * blockDim.x + threadIdx.x;
    if (idx >= IMG_ELEMS) return;
    unsigned off; const float* W; int ind, kpad;
    if      (idx < IOFF_L1)  { off = IOFF_L0;  W = W0; ind = 63;  kpad = 64;  }
    else if (idx < IOFF_L2)  { off = IOFF_L1;  W = W1; ind = 256; kpad = 256; }
    else if (idx < IOFF_L3)  { off = IOFF_L2;  W = W2; ind = 256; kpad = 256; }
    else if (idx < IOFF_L4)  { off = IOFF_L3;  W = W3; ind = 256; kpad = 256; }
    else if (idx < IOFF_L5)  { off = IOFF_L4;  W = W4; ind = 319; kpad = 320; }
    else if (idx < IOFF_L6)  { off = IOFF_L5;  W = W5; ind = 256; kpad = 256; }
    else if (idx < IOFF_L7)  { off = IOFF_L6;  W = W6; ind = 256; kpad = 256; }
    else if (idx < IOFF_FT)  { off = IOFF_L7;  W = W7; ind = 256; kpad = 256; }
    else if (idx < IOFF_DIR) { off = IOFF_FT;  W = W8; ind = 256; kpad = 256; }
    else                     { off = IOFF_DIR; W = W9; ind = 283; kpad = 288; }
    unsigned r = idx - off;
    int o = r / kpad, k = r - o * kpad;
    float w = (k < ind) ? __ldg(W + (size_t)o * ind + k) : 0.0f;
    g_w[idx] = __float2half_rn(w);
}

// ---------------- stage one 32-k weight chunk via cp.async ----------------
__device__ __forceinline__ void stage(uint32_t wb, unsigned img_off,
                                      int Kpad, int Nrows, int k0, int tid) {
    int total = Nrows * 4;                       // 16B units
#pragma unroll 1
    for (int idx = tid; idx < total; idx += THREADS) {
        int n = idx >> 2, seg = idx & 3;
        const __half* src = g_w + img_off + (size_t)n * Kpad + k0 + seg * 8;
        cpa16(wb + (n * 40 + seg * 8) * 2, src);
    }
}

// ---------------- one layer ----------------
// M=128: warp mb=(w&1)*64. N=NB*32: warp nb=(w>>1)*NB*8.
// EPI: 0 = relu->act; 1 = relu->act + density partials; 2 = rgb partials only
template<int NB, int EPI>
__device__ __noinline__ void layer(char* smem, uint32_t smb,
                                   unsigned img_off, const float* __restrict__ bias_g,
                                   int Kpad, int nc, int xc, int estr) {
    const int tid  = threadIdx.x;
    const int lane = tid & 31;
    const int w    = tid >> 5;
    const int N    = NB * 32;
    const int mb   = (w & 1) * 64;
    const int nb   = (w >> 1) * (NB * 8);

    float acc[4][NB][4];
#pragma unroll
    for (int i = 0; i < 4; ++i)
#pragma unroll
        for (int j = 0; j < NB; ++j)
#pragma unroll
            for (int r = 0; r < 4; ++r) acc[i][j][r] = 0.0f;

    if (tid < N) ((float*)(smem + SM_BIAS))[tid] = __ldg(bias_g + tid);
    stage(smb + SM_WBUF, img_off, Kpad, N, 0, tid);
    CP_COMMIT();

    const int m_off  = (lane & 7) + ((lane >> 3) & 1) * 8;
    const int ak_off = (lane >> 4) * 8;
    const int n_off  = (lane & 7) + ((lane >> 4) << 3);
    const int bk_off = ((lane >> 3) & 1) * 8;

#pragma unroll 1
    for (int c = 0; c < nc; ++c) {
        CP_WAIT0();
        __syncthreads();
        if (c + 1 < nc) {
            stage(smb + SM_WBUF + ((c + 1) & 1) * 20480, img_off, Kpad, N, (c + 1) * 32, tid);
            CP_COMMIT();
        }
        uint32_t ab; int astr, koff;
        if (c < xc) { ab = smb + SM_ACT; astr = 264;  koff = c * 32; }
        else        { ab = smb + SM_EMB; astr = estr; koff = (c - xc) * 32; }
        uint32_t wb = smb + SM_WBUF + (c & 1) * 20480;

#pragma unroll
        for (int ks = 0; ks < 2; ++ks) {
            int kk = koff + ks * 16;
            uint32_t A[4][4];
#pragma unroll
            for (int i = 0; i < 4; ++i)
                ldsm4(A[i], ab + ((mb + i * 16 + m_off) * astr + kk + ak_off) * 2);
#pragma unroll
            for (int jp = 0; jp < NB / 2; ++jp) {
                uint32_t B[4];
                ldsm4(B, wb + ((nb + jp * 16 + n_off) * 40 + ks * 16 + bk_off) * 2);
#pragma unroll
                for (int i = 0; i < 4; ++i)
#pragma unroll
                    for (int jj = 0; jj < 2; ++jj)
                        mma_f16(acc[i][jp * 2 + jj], A[i], &B[jj * 2]);
            }
        }
    }
    __syncthreads();

    // ---- epilogue ----
    const float* bias_s = (const float*)(smem + SM_BIAS);
    float ds[8];
    float pr[24];
    if (EPI == 1) {
#pragma unroll
        for (int q = 0; q < 8; ++q) ds[q] = 0.0f;
    }
    if (EPI == 2) {
#pragma unroll
        for (int q = 0; q < 24; ++q) pr[q] = 0.0f;
    }
#pragma unroll
    for (int i = 0; i < 4; ++i)
#pragma unroll
    for (int j = 0; j < NB; ++j) {
        int n = nb + j * 8 + (lane & 3) * 2;
        float bx = bias_s[n], by = bias_s[n + 1];
        float r00 = fmaxf(acc[i][j][0] + bx, 0.0f);
        float r01 = fmaxf(acc[i][j][1] + by, 0.0f);
        float r10 = fmaxf(acc[i][j][2] + bx, 0.0f);
        float r11 = fmaxf(acc[i][j][3] + by, 0.0f);
        if (EPI != 2) {
            int m0 = mb + i * 16 + (lane >> 2);
            *(uint32_t*)(smem + SM_ACT + (m0 * 264 + n) * 2)       = packh(r00, r01);
            *(uint32_t*)(smem + SM_ACT + ((m0 + 8) * 264 + n) * 2) = packh(r10, r11);
        }
        if (EPI == 1) {
            const float* wd = (const float*)(smem + SM_WDEN);
            ds[i * 2 + 0] += r00 * wd[n] + r01 * wd[n + 1];
            ds[i * 2 + 1] += r10 * wd[n] + r11 * wd[n + 1];
        }
        if (EPI == 2) {
            const float* wr = (const float*)(smem + SM_WRGB);
#pragma unroll
            for (int ch = 0; ch < 3; ++ch) {
                pr[(i * 2 + 0) * 3 + ch] += r00 * wr[ch * 128 + n] + r01 * wr[ch * 128 + n + 1];
                pr[(i * 2 + 1) * 3 + ch] += r10 * wr[ch * 128 + n] + r11 * wr[ch * 128 + n + 1];
            }
        }
    }
    if (EPI == 1) {
#pragma unroll
        for (int q = 0; q < 8; ++q) {
            ds[q] += __shfl_xor_sync(0xffffffffu, ds[q], 1);
            ds[q] += __shfl_xor_sync(0xffffffffu, ds[q], 2);
        }
        if ((lane & 3) == 0) {
            float* dp = (float*)(smem + SM_DENSP);
#pragma unroll
            for (int i = 0; i < 4; ++i)
#pragma unroll
            for (int h2 = 0; h2 < 2; ++h2)
                dp[(w >> 1) * 128 + mb + i * 16 + h2 * 8 + (lane >> 2)] = ds[i * 2 + h2];
        }
    }
    if (EPI == 2) {
#pragma unroll
        for (int q = 0; q < 24; ++q) {
            pr[q] += __shfl_xor_sync(0xffffffffu, pr[q], 1);
            pr[q] += __shfl_xor_sync(0xffffffffu, pr[q], 2);
        }
        if ((lane & 3) == 0) {
            float* rp = (float*)(smem + SM_RGBP);
#pragma unroll
            for (int i = 0; i < 4; ++i)
#pragma unroll
            for (int h2 = 0; h2 < 2; ++h2)
#pragma unroll
            for (int ch = 0; ch < 3; ++ch)
                rp[(ch * 4 + (w >> 1)) * 128 + mb + i * 16 + h2 * 8 + (lane >> 2)]
                    = pr[(i * 2 + h2) * 3 + ch];
        }
    }
    __syncthreads();
}

// ---------------- main fused kernel ----------------
__global__ void __launch_bounds__(THREADS, 1) nerf_hmma(
    const float* __restrict__ sp,   const float* __restrict__ dirs,
    const float* __restrict__ bx0,  const float* __restrict__ bx1,
    const float* __restrict__ bx2,  const float* __restrict__ bx3,
    const float* __restrict__ bx4,  const float* __restrict__ bx5,
    const float* __restrict__ bx6,  const float* __restrict__ bx7,
    const float* __restrict__ bd0,  const float* __restrict__ bden,
    const float* __restrict__ bfeat,const float* __restrict__ brgb,
    const float* __restrict__ Wden, const float* __restrict__ Wrgb,
    float* __restrict__ out)
{
    extern __shared__ char smem[];
    uint32_t smb = s2u(smem);
    const int tid = threadIdx.x;
    const int p0  = blockIdx.x * NSAMP;

    // xyz harmonic embedding -> fp16 tile [128][72]
    if (tid < NSAMP) {
        float e[64];
        const float* pp = sp + (size_t)(p0 + tid) * 3;
#pragma unroll
        for (int d = 0; d < 3; ++d) {
            float x = pp[d], f = 1.0f;
#pragma unroll
            for (int h = 0; h < 10; ++h) {
                float s, c;
                sincosf(x * f, &s, &c);
                e[d * 10 + h] = s;
                e[30 + d * 10 + h] = c;
                f *= 2.0f;
            }
            e[60 + d] = x;
        }
        e[63] = 0.0f;
#pragma unroll
        for (int k = 0; k < 32; ++k)
            *(uint32_t*)(smem + SM_EMB + (tid * 72 + k * 2) * 2) = packh(e[2 * k], e[2 * k + 1]);
    }
    if (tid < 256) ((float*)(smem + SM_WDEN))[tid] = __ldg(Wden + tid);
    if (tid < 256) ((float*)(smem + SM_WRGB))[tid] = __ldg(Wrgb + tid);
    if (tid < 128) ((float*)(smem + SM_WRGB))[256 + tid] = __ldg(Wrgb + 256 + tid);
    // first layer's CP_WAIT+__syncthreads orders the above before any read

    layer<8, 0>(smem, smb, IOFF_L0, bx0,  64,  2, 0, 72);
    layer<8, 0>(smem, smb, IOFF_L1, bx1, 256,  8, 8, 72);
    layer<8, 0>(smem, smb, IOFF_L2, bx2, 256,  8, 8, 72);
    layer<8, 0>(smem, smb, IOFF_L3, bx3, 256,  8, 8, 72);
    layer<8, 0>(smem, smb, IOFF_L4, bx4, 320, 10, 8, 72);   // skip concat
    layer<8, 0>(smem, smb, IOFF_L5, bx5, 256,  8, 8, 72);
    layer<8, 0>(smem, smb, IOFF_L6, bx6, 256,  8, 8, 72);
    layer<8, 1>(smem, smb, IOFF_L7, bx7, 256,  8, 8, 72);   // + density partials

    if (tid < NSAMP) {
        const float* dp = (const float*)(smem + SM_DENSP);
        float s = dp[tid] + dp[128 + tid] + dp[256 + tid] + dp[384 + tid] + __ldg(bden);
        ((float*)(smem + SM_DENS))[tid] = fmaxf(s, 0.0f);
    }

    layer<8, 0>(smem, smb, IOFF_FT, bfeat, 256, 8, 8, 72);

    // direction embedding: 2 rays per CTA -> scratch[2][32] -> [128][40] fp16 tile
    if (tid < 64) {
        int ray = tid >> 5, kk = tid & 31;
        float v = 0.0f;
        if (kk < 12) {
            float x = __ldg(dirs + (size_t)(blockIdx.x * 2 + ray) * 3 + (kk >> 2));
            v = sinf(x * (float)(1 << (kk & 3)));
        } else if (kk < 24) {
            int q = kk - 12;
            float x = __ldg(dirs + (size_t)(blockIdx.x * 2 + ray) * 3 + (q >> 2));
            v = cosf(x * (float)(1 << (q & 3)));
        } else if (kk < 27) {
            v = __ldg(dirs + (size_t)(blockIdx.x * 2 + ray) * 3 + (kk - 24));
        }
        ((float*)(smem + SM_DIRS))[tid] = v;
    }
    __syncthreads();
#pragma unroll 1
    for (int idx = tid; idx < NSAMP * 16; idx += THREADS) {
        int row = idx >> 4, k2 = idx & 15;
        const float* sc = (const float*)(smem + SM_DIRS) + (row >> 6) * 32;
        *(uint32_t*)(smem + SM_EMB + (row * 40 + k2 * 2) * 2) = packh(sc[2 * k2], sc[2 * k2 + 1]);
    }
    __syncthreads();

    layer<4, 2>(smem, smb, IOFF_DIR, bd0, 288, 9, 8, 40);   // rgb partials

    if (tid < NSAMP) {
        const float* rp = (const float*)(smem + SM_RGBP);
        float* op = out + (size_t)(p0 + tid) * 4;
        op[0] = ((const float*)(smem + SM_DENS))[tid];
#pragma unroll
        for (int ch = 0; ch < 3; ++ch) {
            float s = rp[(ch * 4 + 0) * 128 + tid] + rp[(ch * 4 + 1) * 128 + tid]
                    + rp[(ch * 4 + 2) * 128 + tid] + rp[(ch * 4 + 3) * 128 + tid]
                    + __ldg(brgb + ch);
            op[1 + ch] = 1.0f / (1.0f + expf(-s));
        }
    }
}

extern "C" void kernel_launch(void* const* d_in, const int* in_sizes, int n_in,
                              void* d_out, int out_size) {
    (void)in_sizes; (void)n_in; (void)out_size;
    prep_all<<<(IMG_ELEMS + 255) / 256, 256>>>(
        (const float*)d_in[2],  (const float*)d_in[4],
        (const float*)d_in[6],  (const float*)d_in[8],
        (const float*)d_in[10], (const float*)d_in[12],
        (const float*)d_in[14], (const float*)d_in[16],
        (const float*)d_in[22],   // Wfeat
        (const float*)d_in[18]);  // Wd0

    cudaFuncSetAttribute(nerf_hmma, cudaFuncAttributeMaxDynamicSharedMemorySize, SMEM_BYTES);
    nerf_hmma<<<GRID, THREADS, SMEM_BYTES>>>(
        (const float*)d_in[0],  (const float*)d_in[1],
        (const float*)d_in[3],  (const float*)d_in[5],
        (const float*)d_in[7],  (const float*)d_in[9],
        (const float*)d_in[11], (const float*)d_in[13],
        (const float*)d_in[15], (const float*)d_in[17],
        (const float*)d_in[19], (const float*)d_in[21],
        (const float*)d_in[23], (const float*)d_in[25],
        (const float*)d_in[20],   // Wden
        (const float*)d_in[24],   // Wrgb
        (float*)d_out);
}

// round 12
// speedup vs baseline: 10.4409x; 1.0282x over previous
#include <cuda_runtime.h>
#include <cuda_fp16.h>
#include <math.h>
#include <stdint.h>

#define THREADS 512
#define GRID    2048
#define NSAMP   128

// ---------------- weight image (fp16, K zero-padded) ----------------
#define IOFF_L0   0u
#define IOFF_L1   16384u
#define IOFF_L2   81920u
#define IOFF_L3   147456u
#define IOFF_L4   212992u
#define IOFF_L5   294912u
#define IOFF_L6   360448u
#define IOFF_L7   425984u
#define IOFF_FT   491520u
#define IOFF_DIR  557056u
#define IMG_ELEMS 593920u

__device__ __align__(16) __half g_w[IMG_ELEMS];

// ---------------- smem layout (bytes) ----------------
#define SM_ACT   0        // [128][264] fp16 activations (stride 528B, ldsm conflict-free)
#define SM_WBUF  67584    // 2 bufs x 20480B: [256n][40 el] per 32-k chunk
#define SM_EMB   108544   // [128][72] fp16 xyz emb; reused as [128][40] dir emb
#define SM_BIAS  126976   // 256 f32
#define SM_WDEN  128000   // 256 f32
#define SM_WRGB  129024   // 384 f32
#define SM_DENSP 130560   // 4x128 f32
#define SM_RGBP  132608   // 12x128 f32
#define SM_DENS  138752   // 128 f32
#define SM_DIRS  139264   // 2x32 f32
#define SMEM_BYTES 139520

// ---------------- low-level helpers ----------------
__device__ __forceinline__ uint32_t s2u(const void* p) {
    uint32_t a;
    asm("{ .reg .u64 t; cvta.to.shared.u64 t, %1; cvt.u32.u64 %0, t; }" : "=r"(a) : "l"(p));
    return a;
}
__device__ __forceinline__ void ldsm4(uint32_t* r, uint32_t a) {
    asm volatile("ldmatrix.sync.aligned.m8n8.x4.shared.b16 {%0,%1,%2,%3}, [%4];"
        : "=r"(r[0]), "=r"(r[1]), "=r"(r[2]), "=r"(r[3]) : "r"(a));
}
__device__ __forceinline__ void mma_f16(float* c, const uint32_t* a, const uint32_t* b) {
    asm volatile("mma.sync.aligned.m16n8k16.row.col.f32.f16.f16.f32 "
        "{%0,%1,%2,%3},{%4,%5,%6,%7},{%8,%9},{%0,%1,%2,%3};"
        : "+f"(c[0]), "+f"(c[1]), "+f"(c[2]), "+f"(c[3])
        : "r"(a[0]), "r"(a[1]), "r"(a[2]), "r"(a[3]), "r"(b[0]), "r"(b[1]));
}
__device__ __forceinline__ void cpa16(uint32_t dst, const void* src) {
    asm volatile("cp.async.cg.shared.global [%0], [%1], 16;" :: "r"(dst), "l"(src));
}
#define CP_COMMIT() asm volatile("cp.async.commit_group;" ::: "memory")
#define CP_WAIT0()  asm volatile("cp.async.wait_group 0;" ::: "memory")

__device__ __forceinline__ uint32_t packh(float x, float y) {
    __half2 h = __floats2half2_rn(x, y);
    return *reinterpret_cast<uint32_t*>(&h);
}

// ---------------- fused weight prep: fp32 -> fp16, one launch ----------------
__global__ void prep_all(const float* __restrict__ W0, const float* __restrict__ W1,
                         const float* __restrict__ W2, const float* __restrict__ W3,
                         const float* __restrict__ W4, const float* __restrict__ W5,
                         const float* __restrict__ W6, const float* __restrict__ W7,
                         const float* __restrict__ W8, const float* __restrict__ W9) {
    unsigned idx = blockIdx.x * blockDim.x + threadIdx.x;
    if (idx >= IMG_ELEMS) return;
    unsigned off; const float* W; int ind, kpad;
    if      (idx < IOFF_L1)  { off = IOFF_L0;  W = W0; ind = 63;  kpad = 64;  }
    else if (idx < IOFF_L2)  { off = IOFF_L1;  W = W1; ind = 256; kpad = 256; }
    else if (idx < IOFF_L3)  { off = IOFF_L2;  W = W2; ind = 256; kpad = 256; }
    else if (idx < IOFF_L4)  { off = IOFF_L3;  W = W3; ind = 256; kpad = 256; }
    else if (idx < IOFF_L5)  { off = IOFF_L4;  W = W4; ind = 319; kpad = 320; }
    else if (idx < IOFF_L6)  { off = IOFF_L5;  W = W5; ind = 256; kpad = 256; }
    else if (idx < IOFF_L7)  { off = IOFF_L6;  W = W6; ind = 256; kpad = 256; }
    else if (idx < IOFF_FT)  { off = IOFF_L7;  W = W7; ind = 256; kpad = 256; }
    else if (idx < IOFF_DIR) { off = IOFF_FT;  W = W8; ind = 256; kpad = 256; }
    else                     { off = IOFF_DIR; W = W9; ind = 283; kpad = 288; }
    unsigned r = idx - off;
    int o = r / kpad, k = r - o * kpad;
    float w = (k < ind) ? __ldg(W + (size_t)o * ind + k) : 0.0f;
    g_w[idx] = __float2half_rn(w);
}

// ---------------- stage one 32-k weight chunk via cp.async ----------------
__device__ __forceinline__ void stage(uint32_t wb, unsigned img_off,
                                      int Kpad, int Nrows, int k0, int tid) {
    int total = Nrows * 4;                       // 16B units
#pragma unroll 1
    for (int idx = tid; idx < total; idx += THREADS) {
        int n = idx >> 2, seg = idx & 3;
        const __half* src = g_w + img_off + (size_t)n * Kpad + k0 + seg * 8;
        cpa16(wb + (n * 40 + seg * 8) * 2, src);
    }
}

// ---------------- one layer ----------------
// 16 warps: wm = w&3 -> m-block wm*32 (2 m16 tiles); wn = w>>2 -> n-block wn*(NB*8).
// N = NB*32 total; per-warp covers NB n8-tiles (NB*8 cols).
// EPI: 0 = relu->act; 1 = relu->act + density partials; 2 = rgb partials only
template<int NB, int EPI>
__device__ __noinline__ void layer(char* smem, uint32_t smb,
                                   unsigned img_off, const float* __restrict__ bias_g,
                                   int Kpad, int nc, int xc, int estr) {
    const int tid  = threadIdx.x;
    const int lane = tid & 31;
    const int w    = tid >> 5;
    const int N    = NB * 32;
    const int mb   = (w & 3) * 32;
    const int nb   = (w >> 2) * (NB * 8);

    float acc[2][NB][4];
#pragma unroll
    for (int i = 0; i < 2; ++i)
#pragma unroll
        for (int j = 0; j < NB; ++j)
#pragma unroll
            for (int r = 0; r < 4; ++r) acc[i][j][r] = 0.0f;

    if (tid < N) ((float*)(smem + SM_BIAS))[tid] = __ldg(bias_g + tid);
    stage(smb + SM_WBUF, img_off, Kpad, N, 0, tid);
    CP_COMMIT();

    const int m_off  = (lane & 7) + ((lane >> 3) & 1) * 8;
    const int ak_off = (lane >> 4) * 8;
    const int n_off  = (lane & 7) + ((lane >> 4) << 3);
    const int bk_off = ((lane >> 3) & 1) * 8;

#pragma unroll 1
    for (int c = 0; c < nc; ++c) {
        CP_WAIT0();
        __syncthreads();
        if (c + 1 < nc) {
            stage(smb + SM_WBUF + ((c + 1) & 1) * 20480, img_off, Kpad, N, (c + 1) * 32, tid);
            CP_COMMIT();
        }
        uint32_t ab; int astr, koff;
        if (c < xc) { ab = smb + SM_ACT; astr = 264;  koff = c * 32; }
        else        { ab = smb + SM_EMB; astr = estr; koff = (c - xc) * 32; }
        uint32_t wb = smb + SM_WBUF + (c & 1) * 20480;

#pragma unroll
        for (int ks = 0; ks < 2; ++ks) {
            int kk = koff + ks * 16;
            uint32_t A[2][4];
#pragma unroll
            for (int i = 0; i < 2; ++i)
                ldsm4(A[i], ab + ((mb + i * 16 + m_off) * astr + kk + ak_off) * 2);
#pragma unroll
            for (int jp = 0; jp < NB / 2; ++jp) {
                uint32_t B[4];
                ldsm4(B, wb + ((nb + jp * 16 + n_off) * 40 + ks * 16 + bk_off) * 2);
#pragma unroll
                for (int i = 0; i < 2; ++i)
#pragma unroll
                    for (int jj = 0; jj < 2; ++jj)
                        mma_f16(acc[i][jp * 2 + jj], A[i], &B[jj * 2]);
            }
        }
    }
    __syncthreads();

    // ---- epilogue ----
    const float* bias_s = (const float*)(smem + SM_BIAS);
    float ds[4];
    float pr[12];
    if (EPI == 1) {
#pragma unroll
        for (int q = 0; q < 4; ++q) ds[q] = 0.0f;
    }
    if (EPI == 2) {
#pragma unroll
        for (int q = 0; q < 12; ++q) pr[q] = 0.0f;
    }
#pragma unroll
    for (int i = 0; i < 2; ++i)
#pragma unroll
    for (int j = 0; j < NB; ++j) {
        int n = nb + j * 8 + (lane & 3) * 2;
        float bx = bias_s[n], by = bias_s[n + 1];
        float r00 = fmaxf(acc[i][j][0] + bx, 0.0f);
        float r01 = fmaxf(acc[i][j][1] + by, 0.0f);
        float r10 = fmaxf(acc[i][j][2] + bx, 0.0f);
        float r11 = fmaxf(acc[i][j][3] + by, 0.0f);
        if (EPI != 2) {
            int m0 = mb + i * 16 + (lane >> 2);
            *(uint32_t*)(smem + SM_ACT + (m0 * 264 + n) * 2)       = packh(r00, r01);
            *(uint32_t*)(smem + SM_ACT + ((m0 + 8) * 264 + n) * 2) = packh(r10, r11);
        }
        if (EPI == 1) {
            const float* wd = (const float*)(smem + SM_WDEN);
            ds[i * 2 + 0] += r00 * wd[n] + r01 * wd[n + 1];
            ds[i * 2 + 1] += r10 * wd[n] + r11 * wd[n + 1];
        }
        if (EPI == 2) {
            const float* wr = (const float*)(smem + SM_WRGB);
#pragma unroll
            for (int ch = 0; ch < 3; ++ch) {
                pr[(i * 2 + 0) * 3 + ch] += r00 * wr[ch * 128 + n] + r01 * wr[ch * 128 + n + 1];
                pr[(i * 2 + 1) * 3 + ch] += r10 * wr[ch * 128 + n] + r11 * wr[ch * 128 + n + 1];
            }
        }
    }
    if (EPI == 1) {
#pragma unroll
        for (int q = 0; q < 4; ++q) {
            ds[q] += __shfl_xor_sync(0xffffffffu, ds[q], 1);
            ds[q] += __shfl_xor_sync(0xffffffffu, ds[q], 2);
        }
        if ((lane & 3) == 0) {
            float* dp = (float*)(smem + SM_DENSP);
#pragma unroll
            for (int i = 0; i < 2; ++i)
#pragma unroll
            for (int h2 = 0; h2 < 2; ++h2)
                dp[(w >> 2) * 128 + mb + i * 16 + h2 * 8 + (lane >> 2)] = ds[i * 2 + h2];
        }
    }
    if (EPI == 2) {
#pragma unroll
        for (int q = 0; q < 12; ++q) {
            pr[q] += __shfl_xor_sync(0xffffffffu, pr[q], 1);
            pr[q] += __shfl_xor_sync(0xffffffffu, pr[q], 2);
        }
        if ((lane & 3) == 0) {
            float* rp = (float*)(smem + SM_RGBP);
#pragma unroll
            for (int i = 0; i < 2; ++i)
#pragma unroll
            for (int h2 = 0; h2 < 2; ++h2)
#pragma unroll
            for (int ch = 0; ch < 3; ++ch)
                rp[(ch * 4 + (w >> 2)) * 128 + mb + i * 16 + h2 * 8 + (lane >> 2)]
                    = pr[(i * 2 + h2) * 3 + ch];
        }
    }
    __syncthreads();
}

// ---------------- main fused kernel ----------------
__global__ void __launch_bounds__(THREADS, 1) nerf_hmma(
    const float* __restrict__ sp,   const float* __restrict__ dirs,
    const float* __restrict__ bx0,  const float* __restrict__ bx1,
    const float* __restrict__ bx2,  const float* __restrict__ bx3,
    const float* __restrict__ bx4,  const float* __restrict__ bx5,
    const float* __restrict__ bx6,  const float* __restrict__ bx7,
    const float* __restrict__ bd0,  const float* __restrict__ bden,
    const float* __restrict__ bfeat,const float* __restrict__ brgb,
    const float* __restrict__ Wden, const float* __restrict__ Wrgb,
    float* __restrict__ out)
{
    extern __shared__ char smem[];
    uint32_t smb = s2u(smem);
    const int tid = threadIdx.x;
    const int p0  = blockIdx.x * NSAMP;

    // xyz harmonic embedding -> fp16 tile [128][72]
    if (tid < NSAMP) {
        float e[64];
        const float* pp = sp + (size_t)(p0 + tid) * 3;
#pragma unroll
        for (int d = 0; d < 3; ++d) {
            float x = pp[d], f = 1.0f;
#pragma unroll
            for (int h = 0; h < 10; ++h) {
                float s, c;
                sincosf(x * f, &s, &c);
                e[d * 10 + h] = s;
                e[30 + d * 10 + h] = c;
                f *= 2.0f;
            }
            e[60 + d] = x;
        }
        e[63] = 0.0f;
#pragma unroll
        for (int k = 0; k < 32; ++k)
            *(uint32_t*)(smem + SM_EMB + (tid * 72 + k * 2) * 2) = packh(e[2 * k], e[2 * k + 1]);
    }
    if (tid < 256) ((float*)(smem + SM_WDEN))[tid] = __ldg(Wden + tid);
    if (tid < 256) ((float*)(smem + SM_WRGB))[tid] = __ldg(Wrgb + tid);
    if (tid < 128) ((float*)(smem + SM_WRGB))[256 + tid] = __ldg(Wrgb + 256 + tid);
    // first layer's CP_WAIT+__syncthreads orders the above before any read

    layer<8, 0>(smem, smb, IOFF_L0, bx0,  64,  2, 0, 72);
    layer<8, 0>(smem, smb, IOFF_L1, bx1, 256,  8, 8, 72);
    layer<8, 0>(smem, smb, IOFF_L2, bx2, 256,  8, 8, 72);
    layer<8, 0>(smem, smb, IOFF_L3, bx3, 256,  8, 8, 72);
    layer<8, 0>(smem, smb, IOFF_L4, bx4, 320, 10, 8, 72);   // skip concat
    layer<8, 0>(smem, smb, IOFF_L5, bx5, 256,  8, 8, 72);
    layer<8, 0>(smem, smb, IOFF_L6, bx6, 256,  8, 8, 72);
    layer<8, 1>(smem, smb, IOFF_L7, bx7, 256,  8, 8, 72);   // + density partials

    if (tid < NSAMP) {
        const float* dp = (const float*)(smem + SM_DENSP);
        float s = dp[tid] + dp[128 + tid] + dp[256 + tid] + dp[384 + tid] + __ldg(bden);
        ((float*)(smem + SM_DENS))[tid] = fmaxf(s, 0.0f);
    }

    layer<8, 0>(smem, smb, IOFF_FT, bfeat, 256, 8, 8, 72);

    // direction embedding: 2 rays per CTA -> scratch[2][32] -> [128][40] fp16 tile
    if (tid < 64) {
        int ray = tid >> 5, kk = tid & 31;
        float v = 0.0f;
        if (kk < 12) {
            float x = __ldg(dirs + (size_t)(blockIdx.x * 2 + ray) * 3 + (kk >> 2));
            v = sinf(x * (float)(1 << (kk & 3)));
        } else if (kk < 24) {
            int q = kk - 12;
            float x = __ldg(dirs + (size_t)(blockIdx.x * 2 + ray) * 3 + (q >> 2));
            v = cosf(x * (float)(1 << (q & 3)));
        } else if (kk < 27) {
            v = __ldg(dirs + (size_t)(blockIdx.x * 2 + ray) * 3 + (kk - 24));
        }
        ((float*)(smem + SM_DIRS))[tid] = v;
    }
    __syncthreads();
#pragma unroll 1
    for (int idx = tid; idx < NSAMP * 16; idx += THREADS) {
        int row = idx >> 4, k2 = idx & 15;
        const float* sc = (const float*)(smem + SM_DIRS) + (row >> 6) * 32;
        *(uint32_t*)(smem + SM_EMB + (row * 40 + k2 * 2) * 2) = packh(sc[2 * k2], sc[2 * k2 + 1]);
    }
    __syncthreads();

    layer<4, 2>(smem, smb, IOFF_DIR, bd0, 288, 9, 8, 40);   // rgb partials

    if (tid < NSAMP) {
        const float* rp = (const float*)(smem + SM_RGBP);
        float* op = out + (size_t)(p0 + tid) * 4;
        op[0] = ((const float*)(smem + SM_DENS))[tid];
#pragma unroll
        for (int ch = 0; ch < 3; ++ch) {
            float s = rp[(ch * 4 + 0) * 128 + tid] + rp[(ch * 4 + 1) * 128 + tid]
                    + rp[(ch * 4 + 2) * 128 + tid] + rp[(ch * 4 + 3) * 128 + tid]
                    + __ldg(brgb + ch);
            op[1 + ch] = 1.0f / (1.0f + expf(-s));
        }
    }
}

extern "C" void kernel_launch(void* const* d_in, const int* in_sizes, int n_in,
                              void* d_out, int out_size) {
    (void)in_sizes; (void)n_in; (void)out_size;
    prep_all<<<(IMG_ELEMS + 255) / 256, 256>>>(
        (const float*)d_in[2],  (const float*)d_in[4],
        (const float*)d_in[6],  (const float*)d_in[8],
        (const float*)d_in[10], (const float*)d_in[12],
        (const float*)d_in[14], (const float*)d_in[16],
        (const float*)d_in[22],   // Wfeat
        (const float*)d_in[18]);  // Wd0

    cudaFuncSetAttribute(nerf_hmma, cudaFuncAttributeMaxDynamicSharedMemorySize, SMEM_BYTES);
    nerf_hmma<<<GRID, THREADS, SMEM_BYTES>>>(
        (const float*)d_in[0],  (const float*)d_in[1],
        (const float*)d_in[3],  (const float*)d_in[5],
        (const float*)d_in[7],  (const float*)d_in[9],
        (const float*)d_in[11], (const float*)d_in[13],
        (const float*)d_in[15], (const float*)d_in[17],
        (const float*)d_in[19], (const float*)d_in[21],
        (const float*)d_in[23], (const float*)d_in[25],
        (const float*)d_in[20],   // Wden
        (const float*)d_in[24],   // Wrgb
        (float*)d_out);
}

// round 13
// speedup vs baseline: 11.5490x; 1.1061x over previous
#include <cuda_runtime.h>
#include <cuda_fp16.h>
#include <math.h>
#include <stdint.h>

#define THREADS 512
#define GRID    2048
#define NSAMP   128

// ---------------- weight image (fp16, K zero-padded) ----------------
#define IOFF_L0   0u
#define IOFF_L1   16384u
#define IOFF_L2   81920u
#define IOFF_L3   147456u
#define IOFF_L4   212992u
#define IOFF_L5   294912u
#define IOFF_L6   360448u
#define IOFF_L7   425984u
#define IOFF_FT   491520u
#define IOFF_DIR  557056u
#define IMG_ELEMS 598016u

__device__ __align__(16) __half g_w[IMG_ELEMS];

// ---------------- smem layout (bytes) ----------------
#define SM_ACT   0        // [128][264] fp16 activations (stride 528B, ldsm conflict-free)
#define SM_WBUF  67584    // 2 bufs x 36864B: [256n][72 el] per 64-k chunk (144B row: conflict-free)
#define WBUF_SZ  36864
#define SM_EMB   141312   // [128][72] fp16 emb (xyz, later dir; stride 72)
#define SM_BIAS  159744   // 256 f32
#define SM_WDEN  160768   // 256 f32
#define SM_WRGB  161792   // 384 f32
#define SM_DENSP 163328   // 4x128 f32
#define SM_RGBP  165376   // 12x128 f32
#define SM_DENS  171520   // 128 f32
#define SM_DIRS  172032   // 2x32 f32
#define SMEM_BYTES 172288

// ---------------- low-level helpers ----------------
__device__ __forceinline__ uint32_t s2u(const void* p) {
    uint32_t a;
    asm("{ .reg .u64 t; cvta.to.shared.u64 t, %1; cvt.u32.u64 %0, t; }" : "=r"(a) : "l"(p));
    return a;
}
__device__ __forceinline__ void ldsm4(uint32_t* r, uint32_t a) {
    asm volatile("ldmatrix.sync.aligned.m8n8.x4.shared.b16 {%0,%1,%2,%3}, [%4];"
        : "=r"(r[0]), "=r"(r[1]), "=r"(r[2]), "=r"(r[3]) : "r"(a));
}
__device__ __forceinline__ void mma_f16(float* c, const uint32_t* a, const uint32_t* b) {
    asm volatile("mma.sync.aligned.m16n8k16.row.col.f32.f16.f16.f32 "
        "{%0,%1,%2,%3},{%4,%5,%6,%7},{%8,%9},{%0,%1,%2,%3};"
        : "+f"(c[0]), "+f"(c[1]), "+f"(c[2]), "+f"(c[3])
        : "r"(a[0]), "r"(a[1]), "r"(a[2]), "r"(a[3]), "r"(b[0]), "r"(b[1]));
}
__device__ __forceinline__ void cpa16(uint32_t dst, const void* src) {
    asm volatile("cp.async.cg.shared.global [%0], [%1], 16;" :: "r"(dst), "l"(src));
}
#define CP_COMMIT() asm volatile("cp.async.commit_group;" ::: "memory")
#define CP_WAIT0()  asm volatile("cp.async.wait_group 0;" ::: "memory")

__device__ __forceinline__ uint32_t packh(float x, float y) {
    __half2 h = __floats2half2_rn(x, y);
    return *reinterpret_cast<uint32_t*>(&h);
}

// ---------------- fused weight prep: fp32 -> fp16, one launch ----------------
__global__ void prep_all(const float* __restrict__ W0, const float* __restrict__ W1,
                         const float* __restrict__ W2, const float* __restrict__ W3,
                         const float* __restrict__ W4, const float* __restrict__ W5,
                         const float* __restrict__ W6, const float* __restrict__ W7,
                         const float* __restrict__ W8, const float* __restrict__ W9) {
    unsigned idx = blockIdx.x * blockDim.x + threadIdx.x;
    if (idx >= IMG_ELEMS) return;
    unsigned off; const float* W; int ind, kpad;
    if      (idx < IOFF_L1)  { off = IOFF_L0;  W = W0; ind = 63;  kpad = 64;  }
    else if (idx < IOFF_L2)  { off = IOFF_L1;  W = W1; ind = 256; kpad = 256; }
    else if (idx < IOFF_L3)  { off = IOFF_L2;  W = W2; ind = 256; kpad = 256; }
    else if (idx < IOFF_L4)  { off = IOFF_L3;  W = W3; ind = 256; kpad = 256; }
    else if (idx < IOFF_L5)  { off = IOFF_L4;  W = W4; ind = 319; kpad = 320; }
    else if (idx < IOFF_L6)  { off = IOFF_L5;  W = W5; ind = 256; kpad = 256; }
    else if (idx < IOFF_L7)  { off = IOFF_L6;  W = W6; ind = 256; kpad = 256; }
    else if (idx < IOFF_FT)  { off = IOFF_L7;  W = W7; ind = 256; kpad = 256; }
    else if (idx < IOFF_DIR) { off = IOFF_FT;  W = W8; ind = 256; kpad = 256; }
    else                     { off = IOFF_DIR; W = W9; ind = 283; kpad = 320; }
    unsigned r = idx - off;
    int o = r / kpad, k = r - o * kpad;
    float w = (k < ind) ? __ldg(W + (size_t)o * ind + k) : 0.0f;
    g_w[idx] = __float2half_rn(w);
}

// ---------------- stage one 64-k weight chunk via cp.async ----------------
__device__ __forceinline__ void stage(uint32_t wb, unsigned img_off,
                                      int Kpad, int Nrows, int k0, int tid) {
    int total = Nrows * 8;                       // 16B units (64k * 2B / 16)
#pragma unroll 1
    for (int idx = tid; idx < total; idx += THREADS) {
        int n = idx >> 3, seg = idx & 7;
        const __half* src = g_w + img_off + (size_t)n * Kpad + k0 + seg * 8;
        cpa16(wb + (n * 72 + seg * 8) * 2, src);
    }
}

// ---------------- one layer ----------------
// 16 warps: wm = w&3 -> m-block wm*32; wn = w>>2 -> n-block wn*(NB*8). N = NB*32.
// K processed in 64-k chunks (one barrier round each); each chunk = two 32-k halves,
// each half sourced from act (c32 < xc32) or emb. nc64 = #64-k chunks, xc32 in 32-k units.
// EPI: 0 = relu->act; 1 = relu->act + density partials; 2 = rgb partials only
template<int NB, int EPI>
__device__ __noinline__ void layer(char* smem, uint32_t smb,
                                   unsigned img_off, const float* __restrict__ bias_g,
                                   int Kpad, int nc64, int xc32) {
    const int tid  = threadIdx.x;
    const int lane = tid & 31;
    const int w    = tid >> 5;
    const int N    = NB * 32;
    const int mb   = (w & 3) * 32;
    const int nb   = (w >> 2) * (NB * 8);

    float acc[2][NB][4];
#pragma unroll
    for (int i = 0; i < 2; ++i)
#pragma unroll
        for (int j = 0; j < NB; ++j)
#pragma unroll
            for (int r = 0; r < 4; ++r) acc[i][j][r] = 0.0f;

    if (tid < N) ((float*)(smem + SM_BIAS))[tid] = __ldg(bias_g + tid);
    stage(smb + SM_WBUF, img_off, Kpad, N, 0, tid);
    CP_COMMIT();

    const int m_off  = (lane & 7) + ((lane >> 3) & 1) * 8;
    const int ak_off = (lane >> 4) * 8;
    const int n_off  = (lane & 7) + ((lane >> 4) << 3);
    const int bk_off = ((lane >> 3) & 1) * 8;

#pragma unroll 1
    for (int c = 0; c < nc64; ++c) {
        CP_WAIT0();
        __syncthreads();
        if (c + 1 < nc64) {
            stage(smb + SM_WBUF + ((c + 1) & 1) * WBUF_SZ, img_off, Kpad, N, (c + 1) * 64, tid);
            CP_COMMIT();
        }
        uint32_t wbuf = smb + SM_WBUF + (c & 1) * WBUF_SZ;

#pragma unroll
        for (int h = 0; h < 2; ++h) {
            int c32 = c * 2 + h;
            uint32_t ab; int astr, koff;
            if (c32 < xc32) { ab = smb + SM_ACT; astr = 264; koff = c32 * 32; }
            else            { ab = smb + SM_EMB; astr = 72;  koff = (c32 - xc32) * 32; }
#pragma unroll
            for (int ks = 0; ks < 2; ++ks) {
                int kk = koff + ks * 16;
                uint32_t A[2][4];
#pragma unroll
                for (int i = 0; i < 2; ++i)
                    ldsm4(A[i], ab + ((mb + i * 16 + m_off) * astr + kk + ak_off) * 2);
#pragma unroll
                for (int jp = 0; jp < NB / 2; ++jp) {
                    uint32_t B[4];
                    ldsm4(B, wbuf + ((nb + jp * 16 + n_off) * 72 + h * 32 + ks * 16 + bk_off) * 2);
#pragma unroll
                    for (int i = 0; i < 2; ++i)
#pragma unroll
                        for (int jj = 0; jj < 2; ++jj)
                            mma_f16(acc[i][jp * 2 + jj], A[i], &B[jj * 2]);
                }
            }
        }
    }
    __syncthreads();

    // ---- epilogue ----
    const float* bias_s = (const float*)(smem + SM_BIAS);
    float ds[4];
    float pr[12];
    if (EPI == 1) {
#pragma unroll
        for (int q = 0; q < 4; ++q) ds[q] = 0.0f;
    }
    if (EPI == 2) {
#pragma unroll
        for (int q = 0; q < 12; ++q) pr[q] = 0.0f;
    }
#pragma unroll
    for (int i = 0; i < 2; ++i)
#pragma unroll
    for (int j = 0; j < NB; ++j) {
        int n = nb + j * 8 + (lane & 3) * 2;
        float bx = bias_s[n], by = bias_s[n + 1];
        float r00 = fmaxf(acc[i][j][0] + bx, 0.0f);
        float r01 = fmaxf(acc[i][j][1] + by, 0.0f);
        float r10 = fmaxf(acc[i][j][2] + bx, 0.0f);
        float r11 = fmaxf(acc[i][j][3] + by, 0.0f);
        if (EPI != 2) {
            int m0 = mb + i * 16 + (lane >> 2);
            *(uint32_t*)(smem + SM_ACT + (m0 * 264 + n) * 2)       = packh(r00, r01);
            *(uint32_t*)(smem + SM_ACT + ((m0 + 8) * 264 + n) * 2) = packh(r10, r11);
        }
        if (EPI == 1) {
            const float* wd = (const float*)(smem + SM_WDEN);
            ds[i * 2 + 0] += r00 * wd[n] + r01 * wd[n + 1];
            ds[i * 2 + 1] += r10 * wd[n] + r11 * wd[n + 1];
        }
        if (EPI == 2) {
            const float* wr = (const float*)(smem + SM_WRGB);
#pragma unroll
            for (int ch = 0; ch < 3; ++ch) {
                pr[(i * 2 + 0) * 3 + ch] += r00 * wr[ch * 128 + n] + r01 * wr[ch * 128 + n + 1];
                pr[(i * 2 + 1) * 3 + ch] += r10 * wr[ch * 128 + n] + r11 * wr[ch * 128 + n + 1];
            }
        }
    }
    if (EPI == 1) {
#pragma unroll
        for (int q = 0; q < 4; ++q) {
            ds[q] += __shfl_xor_sync(0xffffffffu, ds[q], 1);
            ds[q] += __shfl_xor_sync(0xffffffffu, ds[q], 2);
        }
        if ((lane & 3) == 0) {
            float* dp = (float*)(smem + SM_DENSP);
#pragma unroll
            for (int i = 0; i < 2; ++i)
#pragma unroll
            for (int h2 = 0; h2 < 2; ++h2)
                dp[(w >> 2) * 128 + mb + i * 16 + h2 * 8 + (lane >> 2)] = ds[i * 2 + h2];
        }
    }
    if (EPI == 2) {
#pragma unroll
        for (int q = 0; q < 12; ++q) {
            pr[q] += __shfl_xor_sync(0xffffffffu, pr[q], 1);
            pr[q] += __shfl_xor_sync(0xffffffffu, pr[q], 2);
        }
        if ((lane & 3) == 0) {
            float* rp = (float*)(smem + SM_RGBP);
#pragma unroll
            for (int i = 0; i < 2; ++i)
#pragma unroll
            for (int h2 = 0; h2 < 2; ++h2)
#pragma unroll
            for (int ch = 0; ch < 3; ++ch)
                rp[(ch * 4 + (w >> 2)) * 128 + mb + i * 16 + h2 * 8 + (lane >> 2)]
                    = pr[(i * 2 + h2) * 3 + ch];
        }
    }
    __syncthreads();
}

// ---------------- main fused kernel ----------------
__global__ void __launch_bounds__(THREADS, 1) nerf_hmma(
    const float* __restrict__ sp,   const float* __restrict__ dirs,
    const float* __restrict__ bx0,  const float* __restrict__ bx1,
    const float* __restrict__ bx2,  const float* __restrict__ bx3,
    const float* __restrict__ bx4,  const float* __restrict__ bx5,
    const float* __restrict__ bx6,  const float* __restrict__ bx7,
    const float* __restrict__ bd0,  const float* __restrict__ bden,
    const float* __restrict__ bfeat,const float* __restrict__ brgb,
    const float* __restrict__ Wden, const float* __restrict__ Wrgb,
    float* __restrict__ out)
{
    extern __shared__ char smem[];
    uint32_t smb = s2u(smem);
    const int tid = threadIdx.x;
    const int p0  = blockIdx.x * NSAMP;

    // xyz harmonic embedding -> fp16 tile [128][72] (cols 0-63 data, 63 zero)
    if (tid < NSAMP) {
        float e[64];
        const float* pp = sp + (size_t)(p0 + tid) * 3;
#pragma unroll
        for (int d = 0; d < 3; ++d) {
            float x = pp[d], f = 1.0f;
#pragma unroll
            for (int h = 0; h < 10; ++h) {
                float s, c;
                sincosf(x * f, &s, &c);
                e[d * 10 + h] = s;
                e[30 + d * 10 + h] = c;
                f *= 2.0f;
            }
            e[60 + d] = x;
        }
        e[63] = 0.0f;
#pragma unroll
        for (int k = 0; k < 32; ++k)
            *(uint32_t*)(smem + SM_EMB + (tid * 72 + k * 2) * 2) = packh(e[2 * k], e[2 * k + 1]);
    }
    if (tid < 256) ((float*)(smem + SM_WDEN))[tid] = __ldg(Wden + tid);
    if (tid < 256) ((float*)(smem + SM_WRGB))[tid] = __ldg(Wrgb + tid);
    if (tid < 128) ((float*)(smem + SM_WRGB))[256 + tid] = __ldg(Wrgb + 256 + tid);
    // first layer's CP_WAIT+__syncthreads orders the above before any read

    layer<8, 0>(smem, smb, IOFF_L0, bx0,  64, 1, 0);
    layer<8, 0>(smem, smb, IOFF_L1, bx1, 256, 4, 8);
    layer<8, 0>(smem, smb, IOFF_L2, bx2, 256, 4, 8);
    layer<8, 0>(smem, smb, IOFF_L3, bx3, 256, 4, 8);
    layer<8, 0>(smem, smb, IOFF_L4, bx4, 320, 5, 8);   // skip concat
    layer<8, 0>(smem, smb, IOFF_L5, bx5, 256, 4, 8);
    layer<8, 0>(smem, smb, IOFF_L6, bx6, 256, 4, 8);
    layer<8, 1>(smem, smb, IOFF_L7, bx7, 256, 4, 8);   // + density partials

    if (tid < NSAMP) {
        const float* dp = (const float*)(smem + SM_DENSP);
        float s = dp[tid] + dp[128 + tid] + dp[256 + tid] + dp[384 + tid] + __ldg(bden);
        ((float*)(smem + SM_DENS))[tid] = fmaxf(s, 0.0f);
    }

    layer<8, 0>(smem, smb, IOFF_FT, bfeat, 256, 4, 8);

    // direction embedding: 2 rays per CTA -> scratch[2][32] -> [128][72] tile, cols 0-63 (32-63 zero)
    if (tid < 64) {
        int ray = tid >> 5, kk = tid & 31;
        float v = 0.0f;
        if (kk < 12) {
            float x = __ldg(dirs + (size_t)(blockIdx.x * 2 + ray) * 3 + (kk >> 2));
            v = sinf(x * (float)(1 << (kk & 3)));
        } else if (kk < 24) {
            int q = kk - 12;
            float x = __ldg(dirs + (size_t)(blockIdx.x * 2 + ray) * 3 + (q >> 2));
            v = cosf(x * (float)(1 << (q & 3)));
        } else if (kk < 27) {
            v = __ldg(dirs + (size_t)(blockIdx.x * 2 + ray) * 3 + (kk - 24));
        }
        ((float*)(smem + SM_DIRS))[tid] = v;
    }
    __syncthreads();
#pragma unroll 1
    for (int idx = tid; idx < NSAMP * 32; idx += THREADS) {
        int row = idx >> 5, k2 = idx & 31;       // k2 = uint32 index (2 cols each)
        uint32_t v = 0u;
        if (k2 < 16) {
            const float* sc = (const float*)(smem + SM_DIRS) + (row >> 6) * 32;
            v = packh(sc[2 * k2], sc[2 * k2 + 1]);
        }
        *(uint32_t*)(smem + SM_EMB + (row * 72 + k2 * 2) * 2) = v;
    }
    __syncthreads();

    layer<4, 2>(smem, smb, IOFF_DIR, bd0, 320, 5, 8);   // rgb partials

    if (tid < NSAMP) {
        const float* rp = (const float*)(smem + SM_RGBP);
        float* op = out + (size_t)(p0 + tid) * 4;
        op[0] = ((const float*)(smem + SM_DENS))[tid];
#pragma unroll
        for (int ch = 0; ch < 3; ++ch) {
            float s = rp[(ch * 4 + 0) * 128 + tid] + rp[(ch * 4 + 1) * 128 + tid]
                    + rp[(ch * 4 + 2) * 128 + tid] + rp[(ch * 4 + 3) * 128 + tid]
                    + __ldg(brgb + ch);
            op[1 + ch] = 1.0f / (1.0f + expf(-s));
        }
    }
}

extern "C" void kernel_launch(void* const* d_in, const int* in_sizes, int n_in,
                              void* d_out, int out_size) {
    (void)in_sizes; (void)n_in; (void)out_size;
    prep_all<<<(IMG_ELEMS + 255) / 256, 256>>>(
        (const float*)d_in[2],  (const float*)d_in[4],
        (const float*)d_in[6],  (const float*)d_in[8],
        (const float*)d_in[10], (const float*)d_in[12],
        (const float*)d_in[14], (const float*)d_in[16],
        (const float*)d_in[22],   // Wfeat
        (const float*)d_in[18]);  // Wd0

    cudaFuncSetAttribute(nerf_hmma, cudaFuncAttributeMaxDynamicSharedMemorySize, SMEM_BYTES);
    nerf_hmma<<<GRID, THREADS, SMEM_BYTES>>>(
        (const float*)d_in[0],  (const float*)d_in[1],
        (const float*)d_in[3],  (const float*)d_in[5],
        (const float*)d_in[7],  (const float*)d_in[9],
        (const float*)d_in[11], (const float*)d_in[13],
        (const float*)d_in[15], (const float*)d_in[17],
        (const float*)d_in[19], (const float*)d_in[21],
        (const float*)d_in[23], (const float*)d_in[25],
        (const float*)d_in[20],   // Wden
        (const float*)d_in[24],   // Wrgb
        (float*)d_out);
}

// round 14
// speedup vs baseline: 11.8773x; 1.0284x over previous
#include <cuda_runtime.h>
#include <cuda_fp16.h>
#include <math.h>
#include <stdint.h>

#define THREADS 256
#define GRID    4096
#define NSAMP   64

// ---------------- weight image (fp16, K zero-padded) ----------------
#define IOFF_L0   0u
#define IOFF_L1   16384u
#define IOFF_L2   81920u
#define IOFF_L3   147456u
#define IOFF_L4   212992u
#define IOFF_L5   294912u
#define IOFF_L6   360448u
#define IOFF_L7   425984u
#define IOFF_FT   491520u
#define IOFF_DIR  557056u
#define IMG_ELEMS 598016u

__device__ __align__(16) __half g_w[IMG_ELEMS];

// ---------------- smem layout (bytes) ----------------
#define SM_ACT   0        // [64][264] fp16 activations (stride 528B, ldsm conflict-free)
#define SM_WBUF  33792    // 2 bufs x 20480B: [256n][40 el] per 32-k chunk
#define WBUF_SZ  20480
#define SM_EMB   74752    // [64][72] fp16 emb (xyz, later dir; stride 72)
#define SM_BIAS  83968    // 256 f32
#define SM_WDEN  84992    // 256 f32
#define SM_WRGB  86016    // 384 f32
#define SM_DENSP 87552    // 4x64 f32
#define SM_RGBP  88576    // 12x64 f32
#define SM_DENS  91648    // 64 f32
#define SM_DIRS  91904    // 32 f32
#define SMEM_BYTES 92032  // x2 CTAs = 184KB <= 227KB carveout

// ---------------- low-level helpers ----------------
__device__ __forceinline__ uint32_t s2u(const void* p) {
    uint32_t a;
    asm("{ .reg .u64 t; cvta.to.shared.u64 t, %1; cvt.u32.u64 %0, t; }" : "=r"(a) : "l"(p));
    return a;
}
__device__ __forceinline__ void ldsm4(uint32_t* r, uint32_t a) {
    asm volatile("ldmatrix.sync.aligned.m8n8.x4.shared.b16 {%0,%1,%2,%3}, [%4];"
        : "=r"(r[0]), "=r"(r[1]), "=r"(r[2]), "=r"(r[3]) : "r"(a));
}
__device__ __forceinline__ void mma_f16(float* c, const uint32_t* a, const uint32_t* b) {
    asm volatile("mma.sync.aligned.m16n8k16.row.col.f32.f16.f16.f32 "
        "{%0,%1,%2,%3},{%4,%5,%6,%7},{%8,%9},{%0,%1,%2,%3};"
        : "+f"(c[0]), "+f"(c[1]), "+f"(c[2]), "+f"(c[3])
        : "r"(a[0]), "r"(a[1]), "r"(a[2]), "r"(a[3]), "r"(b[0]), "r"(b[1]));
}
__device__ __forceinline__ void cpa16(uint32_t dst, const void* src) {
    asm volatile("cp.async.cg.shared.global [%0], [%1], 16;" :: "r"(dst), "l"(src));
}
#define CP_COMMIT() asm volatile("cp.async.commit_group;" ::: "memory")
#define CP_WAIT0()  asm volatile("cp.async.wait_group 0;" ::: "memory")

__device__ __forceinline__ uint32_t packh(float x, float y) {
    __half2 h = __floats2half2_rn(x, y);
    return *reinterpret_cast<uint32_t*>(&h);
}

// ---------------- fused weight prep: fp32 -> fp16, one launch ----------------
__global__ void prep_all(const float* __restrict__ W0, const float* __restrict__ W1,
                         const float* __restrict__ W2, const float* __restrict__ W3,
                         const float* __restrict__ W4, const float* __restrict__ W5,
                         const float* __restrict__ W6, const float* __restrict__ W7,
                         const float* __restrict__ W8, const float* __restrict__ W9) {
    unsigned idx = blockIdx.x * blockDim.x + threadIdx.x;
    if (idx >= IMG_ELEMS) return;
    unsigned off; const float* W; int ind, kpad;
    if      (idx < IOFF_L1)  { off = IOFF_L0;  W = W0; ind = 63;  kpad = 64;  }
    else if (idx < IOFF_L2)  { off = IOFF_L1;  W = W1; ind = 256; kpad = 256; }
    else if (idx < IOFF_L3)  { off = IOFF_L2;  W = W2; ind = 256; kpad = 256; }
    else if (idx < IOFF_L4)  { off = IOFF_L3;  W = W3; ind = 256; kpad = 256; }
    else if (idx < IOFF_L5)  { off = IOFF_L4;  W = W4; ind = 319; kpad = 320; }
    else if (idx < IOFF_L6)  { off = IOFF_L5;  W = W5; ind = 256; kpad = 256; }
    else if (idx < IOFF_L7)  { off = IOFF_L6;  W = W6; ind = 256; kpad = 256; }
    else if (idx < IOFF_FT)  { off = IOFF_L7;  W = W7; ind = 256; kpad = 256; }
    else if (idx < IOFF_DIR) { off = IOFF_FT;  W = W8; ind = 256; kpad = 256; }
    else                     { off = IOFF_DIR; W = W9; ind = 283; kpad = 320; }
    unsigned r = idx - off;
    int o = r / kpad, k = r - o * kpad;
    float w = (k < ind) ? __ldg(W + (size_t)o * ind + k) : 0.0f;
    g_w[idx] = __float2half_rn(w);
}

// ---------------- stage one 32-k weight chunk via cp.async ----------------
__device__ __forceinline__ void stage(uint32_t wb, unsigned img_off,
                                      int Kpad, int Nrows, int k0, int tid) {
    int total = Nrows * 4;                       // 16B units (32k * 2B / 16)
#pragma unroll 1
    for (int idx = tid; idx < total; idx += THREADS) {
        int n = idx >> 2, seg = idx & 3;
        const __half* src = g_w + img_off + (size_t)n * Kpad + k0 + seg * 8;
        cpa16(wb + (n * 40 + seg * 8) * 2, src);
    }
}

// ---------------- one layer ----------------
// 8 warps: wm = w&1 -> m-block wm*32 (M=64); wn = w>>1 -> n-block wn*(NB*8). N = NB*32.
// EPI: 0 = relu->act; 1 = relu->act + density partials; 2 = rgb partials only
template<int NB, int EPI>
__device__ __noinline__ void layer(char* smem, uint32_t smb,
                                   unsigned img_off, const float* __restrict__ bias_g,
                                   int Kpad, int nc, int xc) {
    const int tid  = threadIdx.x;
    const int lane = tid & 31;
    const int w    = tid >> 5;
    const int N    = NB * 32;
    const int mb   = (w & 1) * 32;
    const int nb   = (w >> 1) * (NB * 8);

    float acc[2][NB][4];
#pragma unroll
    for (int i = 0; i < 2; ++i)
#pragma unroll
        for (int j = 0; j < NB; ++j)
#pragma unroll
            for (int r = 0; r < 4; ++r) acc[i][j][r] = 0.0f;

    if (tid < N) ((float*)(smem + SM_BIAS))[tid] = __ldg(bias_g + tid);
    stage(smb + SM_WBUF, img_off, Kpad, N, 0, tid);
    CP_COMMIT();

    const int m_off  = (lane & 7) + ((lane >> 3) & 1) * 8;
    const int ak_off = (lane >> 4) * 8;
    const int n_off  = (lane & 7) + ((lane >> 4) << 3);
    const int bk_off = ((lane >> 3) & 1) * 8;

#pragma unroll 1
    for (int c = 0; c < nc; ++c) {
        CP_WAIT0();
        __syncthreads();
        if (c + 1 < nc) {
            stage(smb + SM_WBUF + ((c + 1) & 1) * WBUF_SZ, img_off, Kpad, N, (c + 1) * 32, tid);
            CP_COMMIT();
        }
        uint32_t ab; int astr, koff;
        if (c < xc) { ab = smb + SM_ACT; astr = 264; koff = c * 32; }
        else        { ab = smb + SM_EMB; astr = 72;  koff = (c - xc) * 32; }
        uint32_t wbuf = smb + SM_WBUF + (c & 1) * WBUF_SZ;

#pragma unroll
        for (int ks = 0; ks < 2; ++ks) {
            int kk = koff + ks * 16;
            uint32_t A[2][4];
#pragma unroll
            for (int i = 0; i < 2; ++i)
                ldsm4(A[i], ab + ((mb + i * 16 + m_off) * astr + kk + ak_off) * 2);
#pragma unroll
            for (int jp = 0; jp < NB / 2; ++jp) {
                uint32_t B[4];
                ldsm4(B, wbuf + ((nb + jp * 16 + n_off) * 40 + ks * 16 + bk_off) * 2);
#pragma unroll
                for (int i = 0; i < 2; ++i)
#pragma unroll
                    for (int jj = 0; jj < 2; ++jj)
                        mma_f16(acc[i][jp * 2 + jj], A[i], &B[jj * 2]);
            }
        }
    }
    __syncthreads();

    // ---- epilogue ----
    const float* bias_s = (const float*)(smem + SM_BIAS);
    float ds[4];
    float pr[12];
    if (EPI == 1) {
#pragma unroll
        for (int q = 0; q < 4; ++q) ds[q] = 0.0f;
    }
    if (EPI == 2) {
#pragma unroll
        for (int q = 0; q < 12; ++q) pr[q] = 0.0f;
    }
#pragma unroll
    for (int i = 0; i < 2; ++i)
#pragma unroll
    for (int j = 0; j < NB; ++j) {
        int n = nb + j * 8 + (lane & 3) * 2;
        float bx = bias_s[n], by = bias_s[n + 1];
        float r00 = fmaxf(acc[i][j][0] + bx, 0.0f);
        float r01 = fmaxf(acc[i][j][1] + by, 0.0f);
        float r10 = fmaxf(acc[i][j][2] + bx, 0.0f);
        float r11 = fmaxf(acc[i][j][3] + by, 0.0f);
        if (EPI != 2) {
            int m0 = mb + i * 16 + (lane >> 2);
            *(uint32_t*)(smem + SM_ACT + (m0 * 264 + n) * 2)       = packh(r00, r01);
            *(uint32_t*)(smem + SM_ACT + ((m0 + 8) * 264 + n) * 2) = packh(r10, r11);
        }
        if (EPI == 1) {
            const float* wd = (const float*)(smem + SM_WDEN);
            ds[i * 2 + 0] += r00 * wd[n] + r01 * wd[n + 1];
            ds[i * 2 + 1] += r10 * wd[n] + r11 * wd[n + 1];
        }
        if (EPI == 2) {
            const float* wr = (const float*)(smem + SM_WRGB);
#pragma unroll
            for (int ch = 0; ch < 3; ++ch) {
                pr[(i * 2 + 0) * 3 + ch] += r00 * wr[ch * 128 + n] + r01 * wr[ch * 128 + n + 1];
                pr[(i * 2 + 1) * 3 + ch] += r10 * wr[ch * 128 + n] + r11 * wr[ch * 128 + n + 1];
            }
        }
    }
    if (EPI == 1) {
#pragma unroll
        for (int q = 0; q < 4; ++q) {
            ds[q] += __shfl_xor_sync(0xffffffffu, ds[q], 1);
            ds[q] += __shfl_xor_sync(0xffffffffu, ds[q], 2);
        }
        if ((lane & 3) == 0) {
            float* dp = (float*)(smem + SM_DENSP);
#pragma unroll
            for (int i = 0; i < 2; ++i)
#pragma unroll
            for (int h2 = 0; h2 < 2; ++h2)
                dp[(w >> 1) * 64 + mb + i * 16 + h2 * 8 + (lane >> 2)] = ds[i * 2 + h2];
        }
    }
    if (EPI == 2) {
#pragma unroll
        for (int q = 0; q < 12; ++q) {
            pr[q] += __shfl_xor_sync(0xffffffffu, pr[q], 1);
            pr[q] += __shfl_xor_sync(0xffffffffu, pr[q], 2);
        }
        if ((lane & 3) == 0) {
            float* rp = (float*)(smem + SM_RGBP);
#pragma unroll
            for (int i = 0; i < 2; ++i)
#pragma unroll
            for (int h2 = 0; h2 < 2; ++h2)
#pragma unroll
            for (int ch = 0; ch < 3; ++ch)
                rp[(ch * 4 + (w >> 1)) * 64 + mb + i * 16 + h2 * 8 + (lane >> 2)]
                    = pr[(i * 2 + h2) * 3 + ch];
        }
    }
    __syncthreads();
}

// ---------------- main fused kernel ----------------
__global__ void __launch_bounds__(THREADS, 2) nerf_hmma(
    const float* __restrict__ sp,   const float* __restrict__ dirs,
    const float* __restrict__ bx0,  const float* __restrict__ bx1,
    const float* __restrict__ bx2,  const float* __restrict__ bx3,
    const float* __restrict__ bx4,  const float* __restrict__ bx5,
    const float* __restrict__ bx6,  const float* __restrict__ bx7,
    const float* __restrict__ bd0,  const float* __restrict__ bden,
    const float* __restrict__ bfeat,const float* __restrict__ brgb,
    const float* __restrict__ Wden, const float* __restrict__ Wrgb,
    float* __restrict__ out)
{
    extern __shared__ char smem[];
    uint32_t smb = s2u(smem);
    const int tid = threadIdx.x;
    const int p0  = blockIdx.x * NSAMP;

    // xyz harmonic embedding -> fp16 tile [64][72] (cols 0-63 data, col 63 zero)
    if (tid < NSAMP) {
        float e[64];
        const float* pp = sp + (size_t)(p0 + tid) * 3;
#pragma unroll
        for (int d = 0; d < 3; ++d) {
            float x = pp[d], f = 1.0f;
#pragma unroll
            for (int h = 0; h < 10; ++h) {
                float s, c;
                sincosf(x * f, &s, &c);
                e[d * 10 + h] = s;
                e[30 + d * 10 + h] = c;
                f *= 2.0f;
            }
            e[60 + d] = x;
        }
        e[63] = 0.0f;
#pragma unroll
        for (int k = 0; k < 32; ++k)
            *(uint32_t*)(smem + SM_EMB + (tid * 72 + k * 2) * 2) = packh(e[2 * k], e[2 * k + 1]);
    }
    if (tid < 256) ((float*)(smem + SM_WDEN))[tid] = __ldg(Wden + tid);
    if (tid < 256) ((float*)(smem + SM_WRGB))[tid] = __ldg(Wrgb + tid);
    if (tid < 128) ((float*)(smem + SM_WRGB))[256 + tid] = __ldg(Wrgb + 256 + tid);
    // first layer's CP_WAIT+__syncthreads orders the above before any read

    layer<8, 0>(smem, smb, IOFF_L0, bx0,  64,  2, 0);
    layer<8, 0>(smem, smb, IOFF_L1, bx1, 256,  8, 8);
    layer<8, 0>(smem, smb, IOFF_L2, bx2, 256,  8, 8);
    layer<8, 0>(smem, smb, IOFF_L3, bx3, 256,  8, 8);
    layer<8, 0>(smem, smb, IOFF_L4, bx4, 320, 10, 8);   // skip concat
    layer<8, 0>(smem, smb, IOFF_L5, bx5, 256,  8, 8);
    layer<8, 0>(smem, smb, IOFF_L6, bx6, 256,  8, 8);
    layer<8, 1>(smem, smb, IOFF_L7, bx7, 256,  8, 8);   // + density partials

    if (tid < NSAMP) {
        const float* dp = (const float*)(smem + SM_DENSP);
        float s = dp[tid] + dp[64 + tid] + dp[128 + tid] + dp[192 + tid] + __ldg(bden);
        ((float*)(smem + SM_DENS))[tid] = fmaxf(s, 0.0f);
    }

    layer<8, 0>(smem, smb, IOFF_FT, bfeat, 256, 8, 8);

    // direction embedding: 1 ray per CTA -> scratch[32] -> [64][72] tile, cols 0-63 (27 data + zeros)
    if (tid < 32) {
        float v = 0.0f;
        if (tid < 12) {
            float x = __ldg(dirs + (size_t)blockIdx.x * 3 + (tid >> 2));
            v = sinf(x * (float)(1 << (tid & 3)));
        } else if (tid < 24) {
            int q = tid - 12;
            float x = __ldg(dirs + (size_t)blockIdx.x * 3 + (q >> 2));
            v = cosf(x * (float)(1 << (q & 3)));
        } else if (tid < 27) {
            v = __ldg(dirs + (size_t)blockIdx.x * 3 + (tid - 24));
        }
        ((float*)(smem + SM_DIRS))[tid] = v;
    }
    __syncthreads();
#pragma unroll 1
    for (int idx = tid; idx < NSAMP * 32; idx += THREADS) {
        int row = idx >> 5, k2 = idx & 31;       // k2 = uint32 index (2 cols each)
        uint32_t v = 0u;
        if (k2 < 16) {
            const float* sc = (const float*)(smem + SM_DIRS);
            v = packh(sc[2 * k2], sc[2 * k2 + 1]);
        }
        *(uint32_t*)(smem + SM_EMB + (row * 72 + k2 * 2) * 2) = v;
    }
    __syncthreads();

    layer<4, 2>(smem, smb, IOFF_DIR, bd0, 320, 10, 8);   // rgb partials

    if (tid < NSAMP) {
        const float* rp = (const float*)(smem + SM_RGBP);
        float* op = out + (size_t)(p0 + tid) * 4;
        op[0] = ((const float*)(smem + SM_DENS))[tid];
#pragma unroll
        for (int ch = 0; ch < 3; ++ch) {
            float s = rp[(ch * 4 + 0) * 64 + tid] + rp[(ch * 4 + 1) * 64 + tid]
                    + rp[(ch * 4 + 2) * 64 + tid] + rp[(ch * 4 + 3) * 64 + tid]
                    + __ldg(brgb + ch);
            op[1 + ch] = 1.0f / (1.0f + expf(-s));
        }
    }
}

extern "C" void kernel_launch(void* const* d_in, const int* in_sizes, int n_in,
                              void* d_out, int out_size) {
    (void)in_sizes; (void)n_in; (void)out_size;
    prep_all<<<(IMG_ELEMS + 255) / 256, 256>>>(
        (const float*)d_in[2],  (const float*)d_in[4],
        (const float*)d_in[6],  (const float*)d_in[8],
        (const float*)d_in[10], (const float*)d_in[12],
        (const float*)d_in[14], (const float*)d_in[16],
        (const float*)d_in[22],   // Wfeat
        (const float*)d_in[18]);  // Wd0

    cudaFuncSetAttribute(nerf_hmma, cudaFuncAttributeMaxDynamicSharedMemorySize, SMEM_BYTES);
    nerf_hmma<<<GRID, THREADS, SMEM_BYTES>>>(
        (const float*)d_in[0],  (const float*)d_in[1],
        (const float*)d_in[3],  (const float*)d_in[5],
        (const float*)d_in[7],  (const float*)d_in[9],
        (const float*)d_in[11], (const float*)d_in[13],
        (const float*)d_in[15], (const float*)d_in[17],
        (const float*)d_in[19], (const float*)d_in[21],
        (const float*)d_in[23], (const float*)d_in[25],
        (const float*)d_in[20],   // Wden
        (const float*)d_in[24],   // Wrgb
        (float*)d_out);
}

// round 15
// speedup vs baseline: 16.4126x; 1.3819x over previous
#include <cuda_runtime.h>
#include <cuda_fp16.h>
#include <math.h>
#include <stdint.h>

#define THREADS 256
#define GRID    4096
#define NSAMP   64

// ---------------- weight fragment image (fp16, mma-fragment order, K zero-padded) ----------------
#define IOFF_L0   0u
#define IOFF_L1   16384u
#define IOFF_L2   81920u
#define IOFF_L3   147456u
#define IOFF_L4   212992u
#define IOFF_L5   294912u
#define IOFF_L6   360448u
#define IOFF_L7   425984u
#define IOFF_FT   491520u
#define IOFF_DIR  557056u
#define IMG_ELEMS 598016u

// uint4 per (chunk32, n8tile, lane): {b0,b1 of k16-step0, b0,b1 of k16-step1}
__device__ __align__(16) uint4 g_wf[IMG_ELEMS / 8];

// ---------------- smem layout (bytes) ----------------
#define SM_ACT   0        // [64][264] fp16 activations (stride 528B, ldsm conflict-free)
#define SM_EMB   33792    // [64][72] fp16 emb (xyz, later dir; stride 72)
#define SM_DENSP 43008    // 8x64 f32 density partials
#define SM_RGBP  45056    // 24x64 f32 rgb partials (ch*8+w)
#define SM_DENS  51200    // 64 f32
#define SM_DIRS  51456    // 32 f32
#define SMEM_BYTES 51712  // x2 CTAs ~ 103KB

// ---------------- low-level helpers ----------------
__device__ __forceinline__ uint32_t s2u(const void* p) {
    uint32_t a;
    asm("{ .reg .u64 t; cvta.to.shared.u64 t, %1; cvt.u32.u64 %0, t; }" : "=r"(a) : "l"(p));
    return a;
}
__device__ __forceinline__ void ldsm4(uint32_t* r, uint32_t a) {
    asm volatile("ldmatrix.sync.aligned.m8n8.x4.shared.b16 {%0,%1,%2,%3}, [%4];"
        : "=r"(r[0]), "=r"(r[1]), "=r"(r[2]), "=r"(r[3]) : "r"(a));
}
__device__ __forceinline__ void mma_f16(float* c, const uint32_t* a, const uint32_t* b) {
    asm volatile("mma.sync.aligned.m16n8k16.row.col.f32.f16.f16.f32 "
        "{%0,%1,%2,%3},{%4,%5,%6,%7},{%8,%9},{%0,%1,%2,%3};"
        : "+f"(c[0]), "+f"(c[1]), "+f"(c[2]), "+f"(c[3])
        : "r"(a[0]), "r"(a[1]), "r"(a[2]), "r"(a[3]), "r"(b[0]), "r"(b[1]));
}
__device__ __forceinline__ uint32_t packh(float x, float y) {
    __half2 h = __floats2half2_rn(x, y);
    return *reinterpret_cast<uint32_t*>(&h);
}

// ---------------- weight prep: fp32 -> fp16 fragments, one launch ----------------
// Fragment layout per layer (NT = N/8 n8-tiles): uint4 index = (chunk*NT + n8)*32 + lane.
// q-th u32 of the uint4 = b-reg: q0 -> (k16=0, b0), q1 -> (k16=0, b1=k+8), q2/q3 -> k16=1.
// Thread fragment element: n = n8*8 + lane/4, k = chunk*32 + (q>>1)*16 + (q&1)*8 + (lane&3)*2.
__global__ void prep_all(const float* __restrict__ W0, const float* __restrict__ W1,
                         const float* __restrict__ W2, const float* __restrict__ W3,
                         const float* __restrict__ W4, const float* __restrict__ W5,
                         const float* __restrict__ W6, const float* __restrict__ W7,
                         const float* __restrict__ W8, const float* __restrict__ W9) {
    unsigned idx = blockIdx.x * blockDim.x + threadIdx.x;   // u32 index
    if (idx >= IMG_ELEMS / 2) return;
    unsigned e = idx * 2;
    unsigned off; const float* W; int ind, Nrows;
    if      (e < IOFF_L1)  { off = IOFF_L0;  W = W0; ind = 63;  Nrows = 256; }
    else if (e < IOFF_L2)  { off = IOFF_L1;  W = W1; ind = 256; Nrows = 256; }
    else if (e < IOFF_L3)  { off = IOFF_L2;  W = W2; ind = 256; Nrows = 256; }
    else if (e < IOFF_L4)  { off = IOFF_L3;  W = W3; ind = 256; Nrows = 256; }
    else if (e < IOFF_L5)  { off = IOFF_L4;  W = W4; ind = 319; Nrows = 256; }
    else if (e < IOFF_L6)  { off = IOFF_L5;  W = W5; ind = 256; Nrows = 256; }
    else if (e < IOFF_L7)  { off = IOFF_L6;  W = W6; ind = 256; Nrows = 256; }
    else if (e < IOFF_FT)  { off = IOFF_L7;  W = W7; ind = 256; Nrows = 256; }
    else if (e < IOFF_DIR) { off = IOFF_FT;  W = W8; ind = 256; Nrows = 256; }
    else                   { off = IOFF_DIR; W = W9; ind = 283; Nrows = 128; }
    unsigned r = idx - off / 2;
    int NT = Nrows >> 3;
    unsigned f = r >> 2, q = r & 3;
    unsigned per = (unsigned)NT * 32u;
    int chunk = f / per;
    int rem = f - chunk * per;
    int n8 = rem >> 5, ln = rem & 31;
    int n = n8 * 8 + (ln >> 2);
    int k0 = chunk * 32 + ((q >> 1) << 4) + ((q & 1) << 3) + ((ln & 3) << 1);
    float w0 = (k0     < ind) ? __ldg(W + (size_t)n * ind + k0)     : 0.0f;
    float w1 = (k0 + 1 < ind) ? __ldg(W + (size_t)n * ind + k0 + 1) : 0.0f;
    reinterpret_cast<uint32_t*>(g_wf)[idx] = packh(w0, w1);
}

// ---------------- one layer ----------------
// 8 warps, each owns ALL 64 m-rows x a distinct 32n (NB=4 n8-tiles) slice (N=256),
// or 16n (NB=2) for the dir layer (N=128). B fragments straight from L2 via LDG.128.
// Syncs: one at entry (act ready), one after the k-loop (act reads done).
// EPI: 0 = relu->act; 1 = relu->act + density partials; 2 = rgb partials only
template<int NB, int EPI>
__device__ __noinline__ void layer(char* smem, uint32_t smb, unsigned img_u4,
                                   const float* __restrict__ bias_g,
                                   const float* __restrict__ head_g,
                                   int nc, int xc) {
    const int tid  = threadIdx.x;
    const int lane = tid & 31;
    const int w    = tid >> 5;
    const int NT   = NB * 8;          // n8-tiles total
    const int nb   = w * (NB * 8);    // first n column of this warp

    float acc[4][NB][4];
#pragma unroll
    for (int i = 0; i < 4; ++i)
#pragma unroll
        for (int j = 0; j < NB; ++j)
#pragma unroll
            for (int r = 0; r < 4; ++r) acc[i][j][r] = 0.0f;

    __syncthreads();                  // prev layer's act writes visible

    const int m_off  = (lane & 7) + ((lane >> 3) & 1) * 8;
    const int ak_off = (lane >> 4) * 8;

#pragma unroll 1
    for (int c = 0; c < nc; ++c) {
        uint4 F[NB];
        const uint4* fb = g_wf + img_u4 + (unsigned)(c * NT + w * NB) * 32u + lane;
#pragma unroll
        for (int jp = 0; jp < NB; ++jp) F[jp] = __ldg(fb + jp * 32);

        uint32_t ab; int astr, koff;
        if (c < xc) { ab = smb + SM_ACT; astr = 264; koff = c * 32; }
        else        { ab = smb + SM_EMB; astr = 72;  koff = (c - xc) * 32; }

#pragma unroll
        for (int ks = 0; ks < 2; ++ks) {
            int kk = koff + ks * 16;
            uint32_t A[4][4];
#pragma unroll
            for (int i = 0; i < 4; ++i)
                ldsm4(A[i], ab + ((i * 16 + m_off) * astr + kk + ak_off) * 2);
#pragma unroll
            for (int jp = 0; jp < NB; ++jp) {
                uint32_t bb[2];
                bb[0] = ks ? F[jp].z : F[jp].x;
                bb[1] = ks ? F[jp].w : F[jp].y;
#pragma unroll
                for (int i = 0; i < 4; ++i)
                    mma_f16(acc[i][jp], A[i], bb);
            }
        }
    }
    __syncthreads();                  // all act reads done before writeback

    // ---- epilogue ----
    float ds[8];
    float pr[24];
    if (EPI == 1) {
#pragma unroll
        for (int q = 0; q < 8; ++q) ds[q] = 0.0f;
    }
    if (EPI == 2) {
#pragma unroll
        for (int q = 0; q < 24; ++q) pr[q] = 0.0f;
    }
    const int nb0 = nb + (lane & 3) * 2;
#pragma unroll
    for (int j = 0; j < NB; ++j) {
        int n = nb0 + j * 8;
        float2 b2 = __ldg(reinterpret_cast<const float2*>(bias_g + n));
        float2 wd2;
        float2 wr2[3];
        if (EPI == 1) wd2 = __ldg(reinterpret_cast<const float2*>(head_g + n));
        if (EPI == 2) {
#pragma unroll
            for (int ch = 0; ch < 3; ++ch)
                wr2[ch] = __ldg(reinterpret_cast<const float2*>(head_g + ch * 128 + n));
        }
#pragma unroll
        for (int i = 0; i < 4; ++i) {
            float r00 = fmaxf(acc[i][j][0] + b2.x, 0.0f);
            float r01 = fmaxf(acc[i][j][1] + b2.y, 0.0f);
            float r10 = fmaxf(acc[i][j][2] + b2.x, 0.0f);
            float r11 = fmaxf(acc[i][j][3] + b2.y, 0.0f);
            if (EPI != 2) {
                int m0 = i * 16 + (lane >> 2);
                *(uint32_t*)(smem + SM_ACT + (m0 * 264 + n) * 2)       = packh(r00, r01);
                *(uint32_t*)(smem + SM_ACT + ((m0 + 8) * 264 + n) * 2) = packh(r10, r11);
            }
            if (EPI == 1) {
                ds[i * 2 + 0] += r00 * wd2.x + r01 * wd2.y;
                ds[i * 2 + 1] += r10 * wd2.x + r11 * wd2.y;
            }
            if (EPI == 2) {
#pragma unroll
                for (int ch = 0; ch < 3; ++ch) {
                    pr[(i * 2 + 0) * 3 + ch] += r00 * wr2[ch].x + r01 * wr2[ch].y;
                    pr[(i * 2 + 1) * 3 + ch] += r10 * wr2[ch].x + r11 * wr2[ch].y;
                }
            }
        }
    }
    if (EPI == 1) {
#pragma unroll
        for (int q = 0; q < 8; ++q) {
            ds[q] += __shfl_xor_sync(0xffffffffu, ds[q], 1);
            ds[q] += __shfl_xor_sync(0xffffffffu, ds[q], 2);
        }
        if ((lane & 3) == 0) {
            float* dp = (float*)(smem + SM_DENSP);
#pragma unroll
            for (int i = 0; i < 4; ++i)
#pragma unroll
            for (int h2 = 0; h2 < 2; ++h2)
                dp[w * 64 + i * 16 + h2 * 8 + (lane >> 2)] = ds[i * 2 + h2];
        }
    }
    if (EPI == 2) {
#pragma unroll
        for (int q = 0; q < 24; ++q) {
            pr[q] += __shfl_xor_sync(0xffffffffu, pr[q], 1);
            pr[q] += __shfl_xor_sync(0xffffffffu, pr[q], 2);
        }
        if ((lane & 3) == 0) {
            float* rp = (float*)(smem + SM_RGBP);
#pragma unroll
            for (int i = 0; i < 4; ++i)
#pragma unroll
            for (int h2 = 0; h2 < 2; ++h2)
#pragma unroll
            for (int ch = 0; ch < 3; ++ch)
                rp[(ch * 8 + w) * 64 + i * 16 + h2 * 8 + (lane >> 2)]
                    = pr[(i * 2 + h2) * 3 + ch];
        }
    }
}

// ---------------- main fused kernel ----------------
__global__ void __launch_bounds__(THREADS, 2) nerf_hmma(
    const float* __restrict__ sp,   const float* __restrict__ dirs,
    const float* __restrict__ bx0,  const float* __restrict__ bx1,
    const float* __restrict__ bx2,  const float* __restrict__ bx3,
    const float* __restrict__ bx4,  const float* __restrict__ bx5,
    const float* __restrict__ bx6,  const float* __restrict__ bx7,
    const float* __restrict__ bd0,  const float* __restrict__ bden,
    const float* __restrict__ bfeat,const float* __restrict__ brgb,
    const float* __restrict__ Wden, const float* __restrict__ Wrgb,
    float* __restrict__ out)
{
    extern __shared__ char smem[];
    uint32_t smb = s2u(smem);
    const int tid = threadIdx.x;
    const int p0  = blockIdx.x * NSAMP;

    // xyz harmonic embedding -> fp16 tile [64][72] (cols 0-63 data, col 63 zero)
    if (tid < NSAMP) {
        float e[64];
        const float* pp = sp + (size_t)(p0 + tid) * 3;
#pragma unroll
        for (int d = 0; d < 3; ++d) {
            float x = pp[d], f = 1.0f;
#pragma unroll
            for (int h = 0; h < 10; ++h) {
                float s, c;
                sincosf(x * f, &s, &c);
                e[d * 10 + h] = s;
                e[30 + d * 10 + h] = c;
                f *= 2.0f;
            }
            e[60 + d] = x;
        }
        e[63] = 0.0f;
#pragma unroll
        for (int k = 0; k < 32; ++k)
            *(uint32_t*)(smem + SM_EMB + (tid * 72 + k * 2) * 2) = packh(e[2 * k], e[2 * k + 1]);
    }
    // each layer begins with __syncthreads(): emb visible before first reads

    layer<4, 0>(smem, smb, IOFF_L0 / 8u, bx0, 0,  2,  0);
    layer<4, 0>(smem, smb, IOFF_L1 / 8u, bx1, 0,  8,  8);
    layer<4, 0>(smem, smb, IOFF_L2 / 8u, bx2, 0,  8,  8);
    layer<4, 0>(smem, smb, IOFF_L3 / 8u, bx3, 0,  8,  8);
    layer<4, 0>(smem, smb, IOFF_L4 / 8u, bx4, 0, 10,  8);   // skip concat
    layer<4, 0>(smem, smb, IOFF_L5 / 8u, bx5, 0,  8,  8);
    layer<4, 0>(smem, smb, IOFF_L6 / 8u, bx6, 0,  8,  8);
    layer<4, 1>(smem, smb, IOFF_L7 / 8u, bx7, Wden, 8, 8);  // + density partials

    __syncthreads();
    if (tid < NSAMP) {
        const float* dp = (const float*)(smem + SM_DENSP);
        float s = __ldg(bden);
#pragma unroll
        for (int q = 0; q < 8; ++q) s += dp[q * 64 + tid];
        ((float*)(smem + SM_DENS))[tid] = fmaxf(s, 0.0f);
    }

    layer<4, 0>(smem, smb, IOFF_FT / 8u, bfeat, 0, 8, 8);

    // direction embedding: 1 ray per CTA -> scratch[32] -> [64][72] tile cols 0-63 (27 data + zeros)
    if (tid < 32) {
        float v = 0.0f;
        if (tid < 12) {
            float x = __ldg(dirs + (size_t)blockIdx.x * 3 + (tid >> 2));
            v = sinf(x * (float)(1 << (tid & 3)));
        } else if (tid < 24) {
            int q = tid - 12;
            float x = __ldg(dirs + (size_t)blockIdx.x * 3 + (q >> 2));
            v = cosf(x * (float)(1 << (q & 3)));
        } else if (tid < 27) {
            v = __ldg(dirs + (size_t)blockIdx.x * 3 + (tid - 24));
        }
        ((float*)(smem + SM_DIRS))[tid] = v;
    }
    __syncthreads();
#pragma unroll 1
    for (int idx = tid; idx < NSAMP * 32; idx += THREADS) {
        int row = idx >> 5, k2 = idx & 31;       // k2 = uint32 index (2 cols each)
        uint32_t v = 0u;
        if (k2 < 16) {
            const float* sc = (const float*)(smem + SM_DIRS);
            v = packh(sc[2 * k2], sc[2 * k2 + 1]);
        }
        *(uint32_t*)(smem + SM_EMB + (row * 72 + k2 * 2) * 2) = v;
    }
    // dir layer's entry sync makes these writes visible

    layer<2, 2>(smem, smb, IOFF_DIR / 8u, bd0, Wrgb, 10, 8);   // rgb partials

    __syncthreads();
    if (tid < NSAMP) {
        const float* rp = (const float*)(smem + SM_RGBP);
        float* op = out + (size_t)(p0 + tid) * 4;
        op[0] = ((const float*)(smem + SM_DENS))[tid];
#pragma unroll
        for (int ch = 0; ch < 3; ++ch) {
            float s = __ldg(brgb + ch);
#pragma unroll
            for (int q = 0; q < 8; ++q) s += rp[(ch * 8 + q) * 64 + tid];
            op[1 + ch] = 1.0f / (1.0f + expf(-s));
        }
    }
}

extern "C" void kernel_launch(void* const* d_in, const int* in_sizes, int n_in,
                              void* d_out, int out_size) {
    (void)in_sizes; (void)n_in; (void)out_size;
    prep_all<<<(IMG_ELEMS / 2 + 255) / 256, 256>>>(
        (const float*)d_in[2],  (const float*)d_in[4],
        (const float*)d_in[6],  (const float*)d_in[8],
        (const float*)d_in[10], (const float*)d_in[12],
        (const float*)d_in[14], (const float*)d_in[16],
        (const float*)d_in[22],   // Wfeat
        (const float*)d_in[18]);  // Wd0

    cudaFuncSetAttribute(nerf_hmma, cudaFuncAttributeMaxDynamicSharedMemorySize, SMEM_BYTES);
    nerf_hmma<<<GRID, THREADS, SMEM_BYTES>>>(
        (const float*)d_in[0],  (const float*)d_in[1],
        (const float*)d_in[3],  (const float*)d_in[5],
        (const float*)d_in[7],  (const float*)d_in[9],
        (const float*)d_in[11], (const float*)d_in[13],
        (const float*)d_in[15], (const float*)d_in[17],
        (const float*)d_in[19], (const float*)d_in[21],
        (const float*)d_in[23], (const float*)d_in[25],
        (const float*)d_in[20],   // Wden
        (const float*)d_in[24],   // Wrgb
        (float*)d_out);
}